// round 4
// baseline (speedup 1.0000x reference)
#include <cuda_runtime.h>
#include <cstdint>

#define VOCAB_MAX 100000
#define D 64
#define K 32

// Scratch (alloc-free rule: __device__ globals)
__device__ float g_P[(size_t)VOCAB_MAX * D];   // u2e @ W1a
__device__ float g_Q[(size_t)VOCAB_MAX * D];   // u2e @ W1b + b1
__device__ unsigned int g_mask[2097152];       // normalized 32-bit mask per node
__device__ int g_flags[2];                     // [0]=nonbin_int, [1]=nonbin_float

// ---------------- packed f32x2 helpers ----------------
__device__ __forceinline__ unsigned long long pack2(float lo, float hi) {
    unsigned long long r;
    asm("mov.b64 %0, {%1, %2};" : "=l"(r) : "f"(lo), "f"(hi));
    return r;
}
__device__ __forceinline__ void unpack2(unsigned long long v, float& lo, float& hi) {
    asm("mov.b64 {%0, %1}, %2;" : "=f"(lo), "=f"(hi) : "l"(v));
}
__device__ __forceinline__ unsigned long long fma2(unsigned long long a,
                                                   unsigned long long b,
                                                   unsigned long long c) {
    unsigned long long d;
    asm("fma.rn.f32x2 %0, %1, %2, %3;" : "=l"(d) : "l"(a), "l"(b), "l"(c));
    return d;
}

// ---------------- mask dtype detection + normalization ----------------
__global__ void mask_init_kernel() { g_flags[0] = 0; g_flags[1] = 0; }

__global__ void mask_detect_kernel(const unsigned int* __restrict__ buf, int n_words) {
    int nonbin_int = 0, nonbin_float = 0;
    for (int i = blockIdx.x * blockDim.x + threadIdx.x; i < n_words;
         i += gridDim.x * blockDim.x) {
        unsigned int w = buf[i];
        if (w != 0u && w != 1u) nonbin_int = 1;
        if (w != 0u && w != 0x3f800000u) nonbin_float = 1;
    }
    if (nonbin_int)   atomicOr(&g_flags[0], 1);
    if (nonbin_float) atomicOr(&g_flags[1], 1);
}

__global__ void mask_convert_kernel(const void* __restrict__ buf, int n_nodes) {
    int n = blockIdx.x * blockDim.x + threadIdx.x;
    if (n >= n_nodes) return;
    int nonbin_int = g_flags[0], nonbin_float = g_flags[1];
    int mode = (!nonbin_float) ? 0 : ((!nonbin_int) ? 1 : 2);  // 0=f32, 1=i32, 2=bytes
    unsigned int m = 0;
    if (mode == 0) {
        const float* p = (const float*)buf + (size_t)n * K;
        for (int k = 0; k < K; k++) if (p[k] != 0.f) m |= (1u << k);
    } else if (mode == 1) {
        const int* p = (const int*)buf + (size_t)n * K;
        for (int k = 0; k < K; k++) if (p[k] != 0) m |= (1u << k);
    } else {
        const unsigned char* p = (const unsigned char*)buf + (size_t)n * K;
        for (int k = 0; k < K; k++) if (p[k] != 0) m |= (1u << k);
    }
    g_mask[n] = m;
}

// ---------------- precompute P = u2e@W1a, Q = u2e@W1b + b1 ----------------
// Low-register version: u2e row is re-read from L1 per output chunk (no r[64]).
__global__ __launch_bounds__(256) void prep_kernel(const float* __restrict__ u2e,
                                                   const float* __restrict__ W1,
                                                   const float* __restrict__ b1,
                                                   int V) {
    __shared__ ulonglong2 sW1[128 * 16];   // 32KB: W1 [128,64] as f32x2 pairs
    __shared__ float sb1[64];
    {
        const float4* W1v = (const float4*)W1;
        float4* sv = (float4*)sW1;
        for (int i = threadIdx.x; i < 128 * 16; i += 256) sv[i] = W1v[i];
        if (threadIdx.x < 64) sb1[threadIdx.x] = b1[threadIdx.x];
    }
    __syncthreads();

    int v = blockIdx.x * blockDim.x + threadIdx.x;
    if (v >= V) return;

    const float4* __restrict__ row = (const float4*)(u2e + (size_t)v * D);
    float4* Pr = (float4*)(g_P + (size_t)v * D);
    float4* Qr = (float4*)(g_Q + (size_t)v * D);

    // half = 0 -> P (W1 rows [0,64)), half = 1 -> Q (W1 rows [64,128), + b1)
#pragma unroll 1
    for (int half = 0; half < 2; half++) {
        const ulonglong2* Wbase = sW1 + half * 64 * 16;
#pragma unroll 1
        for (int c = 0; c < 4; c++) {
            unsigned long long acc[8];
            if (half == 0) {
#pragma unroll
                for (int j = 0; j < 8; j++) acc[j] = 0ull;
            } else {
#pragma unroll
                for (int j = 0; j < 8; j++)
                    acc[j] = pack2(sb1[c * 16 + 2 * j], sb1[c * 16 + 2 * j + 1]);
            }
#pragma unroll 4
            for (int i4 = 0; i4 < 16; i4++) {
                float4 t = row[i4];                       // L1-resident after first chunk
                const ulonglong2* wr = Wbase + (i4 * 4) * 16 + c * 4;
#pragma unroll
                for (int e = 0; e < 4; e++) {
                    float re = (e == 0) ? t.x : (e == 1) ? t.y : (e == 2) ? t.z : t.w;
                    unsigned long long a2 = pack2(re, re);
                    const ulonglong2* w = wr + e * 16;
#pragma unroll
                    for (int jj = 0; jj < 4; jj++) {
                        ulonglong2 ww = w[jj];
                        acc[2 * jj]     = fma2(a2, ww.x, acc[2 * jj]);
                        acc[2 * jj + 1] = fma2(a2, ww.y, acc[2 * jj + 1]);
                    }
                }
            }
            float4* dst = (half == 0) ? Pr : Qr;
#pragma unroll
            for (int jj = 0; jj < 4; jj++) {
                float a, b, cc, d2;
                unpack2(acc[2 * jj], a, b);
                unpack2(acc[2 * jj + 1], cc, d2);
                dst[c * 4 + jj] = make_float4(a, b, cc, d2);
            }
        }
    }
}

// ---------------- reduce-scatter stage (warp-wide column sums) ----------------
template <int OFF, int HALF>
__device__ __forceinline__ void rs_stage(float* part, int lane) {
    bool up = (lane & OFF) != 0;
#pragma unroll
    for (int j = 0; j < HALF; j++) {
        float send  = up ? part[j] : part[j + HALF];
        float other = __shfl_xor_sync(0xffffffffu, send, OFF);
        float keep  = up ? part[j + HALF] : part[j];
        part[j] = keep + other;
    }
}

// ---------------- main fused kernel: one warp per node, one lane per neighbor ----------------
__global__ __launch_bounds__(128, 4) void agg_kernel(
    const float* __restrict__ u2e,
    const float* __restrict__ W2, const float* __restrict__ b2,
    const float* __restrict__ W3, const float* __restrict__ b3,
    const int* __restrict__ nodes, const int* __restrict__ neigh_idx,
    float* __restrict__ out, int n_nodes) {
    __shared__ ulonglong2 sW2[64 * 16];   // 16KB: W2 [64,64] as f32x2 pairs
    __shared__ float sW3[64];
    __shared__ float sb2[64];
    {
        const float4* W2v = (const float4*)W2;
        float4* sv = (float4*)sW2;
        for (int i = threadIdx.x; i < 1024; i += 128) sv[i] = W2v[i];
        if (threadIdx.x < 64) { sW3[threadIdx.x] = W3[threadIdx.x]; sb2[threadIdx.x] = b2[threadIdx.x]; }
    }
    __syncthreads();

    int warp = threadIdx.x >> 5, lane = threadIdx.x & 31;
    int n = blockIdx.x * 4 + warp;
    if (n >= n_nodes) return;

    int node = nodes[n];                       // uniform per warp
    int idx  = neigh_idx[n * K + lane];        // this lane's neighbor
    unsigned int m = (g_mask[n] >> lane) & 1u;

    // ---- layer 1: h1 = relu(P[idx] + Q[node])  (Q already contains b1) ----
    float h1[D];
    {
        const float4* Pr = (const float4*)(g_P + (size_t)idx * D);
        const float4* Qr = (const float4*)(g_Q + (size_t)node * D);
#pragma unroll
        for (int i = 0; i < 16; i++) {
            float4 p = Pr[i];
            float4 q = Qr[i];
            h1[4 * i + 0] = fmaxf(p.x + q.x, 0.f);
            h1[4 * i + 1] = fmaxf(p.y + q.y, 0.f);
            h1[4 * i + 2] = fmaxf(p.z + q.z, 0.f);
            h1[4 * i + 3] = fmaxf(p.w + q.w, 0.f);
        }
    }

    // ---- layers 2+3 fused, output-chunked: 16 h2 cols at a time ----
    float score = b3[0];
#pragma unroll 1
    for (int c = 0; c < 4; c++) {
        unsigned long long acc[8];
#pragma unroll
        for (int j = 0; j < 8; j++)
            acc[j] = pack2(sb2[c * 16 + 2 * j], sb2[c * 16 + 2 * j + 1]);
#pragma unroll 8
        for (int i = 0; i < 64; i++) {
            unsigned long long a2 = pack2(h1[i], h1[i]);
            const ulonglong2* wr = sW2 + i * 16 + c * 4;
#pragma unroll
            for (int jj = 0; jj < 4; jj++) {
                ulonglong2 w = wr[jj];
                acc[2 * jj]     = fma2(a2, w.x, acc[2 * jj]);
                acc[2 * jj + 1] = fma2(a2, w.y, acc[2 * jj + 1]);
            }
        }
#pragma unroll
        for (int j = 0; j < 8; j++) {
            float lo, hi;
            unpack2(acc[j], lo, hi);
            score = fmaf(fmaxf(lo, 0.f), sW3[c * 16 + 2 * j], score);
            score = fmaf(fmaxf(hi, 0.f), sW3[c * 16 + 2 * j + 1], score);
        }
    }

    // ---- masked softmax across the warp (K = 32 = warp width) ----
    float s = m ? score : -1e30f;
    float mx = s;
#pragma unroll
    for (int o = 16; o; o >>= 1) mx = fmaxf(mx, __shfl_xor_sync(0xffffffffu, mx, o));
    float e = __expf(s - mx);                  // masked lanes underflow to exactly 0
    float sum = e;
#pragma unroll
    for (int o = 16; o; o >>= 1) sum += __shfl_xor_sync(0xffffffffu, sum, o);
    float att = __fdividef(e, sum);

    // ---- out[n] = sum_k att_k * u2e[idx_k] : reduce-scatter over the warp ----
    float part[D];
    {
        const float4* Er = (const float4*)(u2e + (size_t)idx * D);
#pragma unroll
        for (int i = 0; i < 16; i++) {
            float4 v = Er[i];
            part[4 * i + 0] = v.x * att;
            part[4 * i + 1] = v.y * att;
            part[4 * i + 2] = v.z * att;
            part[4 * i + 3] = v.w * att;
        }
    }
    rs_stage<16, 32>(part, lane);
    rs_stage<8, 16>(part, lane);
    rs_stage<4, 8>(part, lane);
    rs_stage<2, 4>(part, lane);
    rs_stage<1, 2>(part, lane);
    ((float2*)out)[n * 32 + lane] = make_float2(part[0], part[1]);
}

// ---------------- launch ----------------
// Input order (metadata): u2e, W1, b1, W2, b2, W3, b3, nodes, neigh_idx, neigh_mask
extern "C" void kernel_launch(void* const* d_in, const int* in_sizes, int n_in,
                              void* d_out, int out_size) {
    const float* u2e = (const float*)d_in[0];
    const float* W1  = (const float*)d_in[1];
    const float* b1  = (const float*)d_in[2];
    const float* W2  = (const float*)d_in[3];
    const float* b2  = (const float*)d_in[4];
    const float* W3  = (const float*)d_in[5];
    const float* b3  = (const float*)d_in[6];
    const int*   nodes     = (const int*)d_in[7];
    const int*   neigh_idx = (const int*)d_in[8];
    const void*  neigh_mask = d_in[9];
    float* out = (float*)d_out;

    int V = in_sizes[0] / D;
    if (V > VOCAB_MAX) V = VOCAB_MAX;
    int n_nodes = in_sizes[7];
    int mask_elems = in_sizes[9];
    int n_words = mask_elems / 4;

    mask_init_kernel<<<1, 1>>>();
    mask_detect_kernel<<<256, 256>>>((const unsigned int*)neigh_mask, n_words);
    mask_convert_kernel<<<(n_nodes + 255) / 256, 256>>>(neigh_mask, n_nodes);
    prep_kernel<<<(V + 255) / 256, 256>>>(u2e, W1, b1, V);
    agg_kernel<<<(n_nodes + 3) / 4, 128>>>(u2e, W2, b2, W3, b3,
                                           nodes, neigh_idx, out, n_nodes);
}

// round 6
// speedup vs baseline: 2.3206x; 2.3206x over previous
#include <cuda_runtime.h>
#include <cuda_bf16.h>
#include <cstdint>

#define D 64
#define K 32
#define VOCAB_MAX 100000

// Scratch (alloc-free rule)
__device__ float g_P[(size_t)VOCAB_MAX * D];   // u2e @ W1a          (bf16-mma, fp32 out)
__device__ float g_Q[(size_t)VOCAB_MAX * D];   // u2e @ W1b + b1
__device__ unsigned int g_mask[2097152];
__device__ int g_flags[2];

// ======================= helpers =======================
__device__ __forceinline__ uint32_t smem_to_u32(const void* p) {
    uint32_t a;
    asm("{ .reg .u64 t; cvta.to.shared.u64 t, %1; cvt.u32.u64 %0, t; }" : "=r"(a) : "l"(p));
    return a;
}
#define CVT_BF16X2_F32(result, a, b) \
    asm("cvt.rn.satfinite.bf16x2.f32 %0, %1, %2;" : "=r"(result) : "f"(b), "f"(a))

#define LDMATRIX_X4(r0, r1, r2, r3, addr) \
    asm volatile("ldmatrix.sync.aligned.m8n8.x4.shared.b16 {%0,%1,%2,%3}, [%4];" \
        : "=r"(r0), "=r"(r1), "=r"(r2), "=r"(r3) : "r"(addr))
#define LDMATRIX_X4_TRANS(r0, r1, r2, r3, addr) \
    asm volatile("ldmatrix.sync.aligned.m8n8.x4.trans.shared.b16 {%0,%1,%2,%3}, [%4];" \
        : "=r"(r0), "=r"(r1), "=r"(r2), "=r"(r3) : "r"(addr))

// D (f32) += A (bf16) x B (bf16); C==D accumulate in place
#define MMA16816(d0, d1, d2, d3, a0, a1, a2, a3, b0, b1) \
    asm volatile("mma.sync.aligned.m16n8k16.row.col.f32.bf16.bf16.f32 " \
        "{%0,%1,%2,%3}, {%4,%5,%6,%7}, {%8,%9}, {%0,%1,%2,%3};" \
        : "+f"(d0), "+f"(d1), "+f"(d2), "+f"(d3) \
        : "r"(a0), "r"(a1), "r"(a2), "r"(a3), "r"(b0), "r"(b1))

// A-tile SMEM layout: row stride 72 bf16 (144B) -> conflict-free ldmatrix
#define ASTRIDE_B 144

// ======================= mask dtype detection + normalization =======================
__global__ void mask_init_kernel() { g_flags[0] = 0; g_flags[1] = 0; }

__global__ void mask_detect_kernel(const unsigned int* __restrict__ buf, int n_words) {
    int nonbin_int = 0, nonbin_float = 0;
    for (int i = blockIdx.x * blockDim.x + threadIdx.x; i < n_words;
         i += gridDim.x * blockDim.x) {
        unsigned int w = buf[i];
        if (w != 0u && w != 1u) nonbin_int = 1;
        if (w != 0u && w != 0x3f800000u) nonbin_float = 1;
    }
    if (nonbin_int)   atomicOr(&g_flags[0], 1);
    if (nonbin_float) atomicOr(&g_flags[1], 1);
}

__global__ void mask_convert_kernel(const void* __restrict__ buf, int n_nodes) {
    int n = blockIdx.x * blockDim.x + threadIdx.x;
    if (n >= n_nodes) return;
    int nonbin_int = g_flags[0], nonbin_float = g_flags[1];
    int mode = (!nonbin_float) ? 0 : ((!nonbin_int) ? 1 : 2);  // 0=f32, 1=i32, 2=bytes
    unsigned int m = 0;
    if (mode == 0) {
        const float* p = (const float*)buf + (size_t)n * K;
        for (int k = 0; k < K; k++) if (p[k] != 0.f) m |= (1u << k);
    } else if (mode == 1) {
        const int* p = (const int*)buf + (size_t)n * K;
        for (int k = 0; k < K; k++) if (p[k] != 0) m |= (1u << k);
    } else {
        const unsigned char* p = (const unsigned char*)buf + (size_t)n * K;
        for (int k = 0; k < K; k++) if (p[k] != 0) m |= (1u << k);
    }
    g_mask[n] = m;
}

// ======================= prep: P = u2e@W1a, Q = u2e@W1b + b1 (HMMA) =======================
// CTA = 4 warps; each warp computes 32 vocab rows. K=64, N=64, bf16 in, fp32 out.
__global__ __launch_bounds__(128) void prep_mma_kernel(const float* __restrict__ u2e,
                                                       const float* __restrict__ W1,
                                                       const float* __restrict__ b1,
                                                       int V) {
    __shared__ __align__(16) unsigned char sA[4][32 * ASTRIDE_B];  // per-warp A tiles
    __shared__ __align__(16) unsigned char sW[128 * ASTRIDE_B];    // W1 [128 k-rows][64 n-cols] bf16
    __shared__ float sb1[64];
    int tid = threadIdx.x, warp = tid >> 5, lane = tid & 31;

    // Stage W1 (bf16, padded rows)
    for (int p = tid; p < 128 * 32; p += 128) {
        int r = p >> 5, cp = p & 31;
        uint32_t v;
        CVT_BF16X2_F32(v, W1[(size_t)r * 64 + 2 * cp], W1[(size_t)r * 64 + 2 * cp + 1]);
        *(uint32_t*)(sW + r * ASTRIDE_B + cp * 4) = v;
    }
    if (tid < 64) sb1[tid] = b1[tid];
    __syncthreads();

    int v0 = (blockIdx.x * 4 + warp) * 32;
    int vr = v0 + lane;
    int vc = (vr < V) ? vr : (V - 1);

    // Stage this lane's u2e row as bf16 into the warp's A tile
    {
        const float4* row = (const float4*)(u2e + (size_t)vc * D);
        unsigned char* dst = sA[warp] + lane * ASTRIDE_B;
#pragma unroll
        for (int i = 0; i < 8; i++) {
            float4 f0 = row[2 * i], f1 = row[2 * i + 1];
            uint4 w;
            CVT_BF16X2_F32(w.x, f0.x, f0.y);
            CVT_BF16X2_F32(w.y, f0.z, f0.w);
            CVT_BF16X2_F32(w.z, f1.x, f1.y);
            CVT_BF16X2_F32(w.w, f1.z, f1.w);
            *(uint4*)(dst + i * 16) = w;
        }
    }
    __syncwarp();

    // Load A fragments: 2 m-tiles x 4 k-steps
    uint32_t af[2][4][4];
    uint32_t a_base = smem_to_u32(sA[warp]);
#pragma unroll
    for (int mt = 0; mt < 2; mt++)
#pragma unroll
        for (int ks = 0; ks < 4; ks++) {
            uint32_t addr = a_base + (mt * 16 + (lane & 15)) * ASTRIDE_B + ks * 32 + (lane >> 4) * 16;
            LDMATRIX_X4(af[mt][ks][0], af[mt][ks][1], af[mt][ks][2], af[mt][ks][3], addr);
        }

    uint32_t w_base = smem_to_u32(sW);
    int j0 = 2 * (lane & 3);
    int r0 = lane >> 2;

#pragma unroll
    for (int half = 0; half < 2; half++) {
        float* gOut = half ? g_Q : g_P;
#pragma unroll
        for (int nt = 0; nt < 8; nt++) {
            // B frags for k0-31 and k32-63 of this n-tile
            uint32_t b[4][2];
            {
                uint32_t r0b, r1b, r2b, r3b;
                uint32_t addr = w_base + (half * 64 + lane) * ASTRIDE_B + nt * 16;
                LDMATRIX_X4_TRANS(r0b, r1b, r2b, r3b, addr);
                b[0][0] = r0b; b[0][1] = r1b; b[1][0] = r2b; b[1][1] = r3b;
                addr = w_base + (half * 64 + 32 + lane) * ASTRIDE_B + nt * 16;
                LDMATRIX_X4_TRANS(r0b, r1b, r2b, r3b, addr);
                b[2][0] = r0b; b[2][1] = r1b; b[3][0] = r2b; b[3][1] = r3b;
            }
            int j = nt * 8 + j0;
            float init0 = half ? sb1[j] : 0.f;
            float init1 = half ? sb1[j + 1] : 0.f;
#pragma unroll
            for (int mt = 0; mt < 2; mt++) {
                float d0 = init0, d1 = init1, d2 = init0, d3 = init1;
#pragma unroll
                for (int ks = 0; ks < 4; ks++)
                    MMA16816(d0, d1, d2, d3,
                             af[mt][ks][0], af[mt][ks][1], af[mt][ks][2], af[mt][ks][3],
                             b[ks][0], b[ks][1]);
                int ra = v0 + mt * 16 + r0;
                int rb = ra + 8;
                if (ra < V) *(float2*)(gOut + (size_t)ra * D + j) = make_float2(d0, d1);
                if (rb < V) *(float2*)(gOut + (size_t)rb * D + j) = make_float2(d2, d3);
            }
        }
    }
}

// ---------------- reduce-scatter stage ----------------
template <int OFF, int HALF>
__device__ __forceinline__ void rs_stage(float* part, int lane) {
    bool up = (lane & OFF) != 0;
#pragma unroll
    for (int j = 0; j < HALF; j++) {
        float send  = up ? part[j] : part[j + HALF];
        float other = __shfl_xor_sync(0xffffffffu, send, OFF);
        float keep  = up ? part[j + HALF] : part[j];
        part[j] = keep + other;
    }
}

// ======================= agg: one warp per node (32 neighbors = 32 MMA rows) ==============
__global__ __launch_bounds__(128) void agg_mma_kernel(
    const float* __restrict__ u2e,
    const float* __restrict__ W2, const float* __restrict__ b2,
    const float* __restrict__ W3, const float* __restrict__ b3,
    const int* __restrict__ nodes, const int* __restrict__ neigh_idx,
    float* __restrict__ out, int n_nodes) {
    __shared__ __align__(16) unsigned char sA[4][32 * ASTRIDE_B];  // per-warp h1 tiles (bf16)
    __shared__ __align__(16) unsigned char sW2[64 * ASTRIDE_B];    // W2 [64 k][64 n] bf16
    __shared__ float sb2[64];
    __shared__ float sW3[64];
    int tid = threadIdx.x, warp = tid >> 5, lane = tid & 31;

    for (int p = tid; p < 64 * 32; p += 128) {
        int r = p >> 5, cp = p & 31;
        uint32_t v;
        CVT_BF16X2_F32(v, W2[(size_t)r * 64 + 2 * cp], W2[(size_t)r * 64 + 2 * cp + 1]);
        *(uint32_t*)(sW2 + r * ASTRIDE_B + cp * 4) = v;
    }
    if (tid < 64) { sb2[tid] = b2[tid]; sW3[tid] = W3[tid]; }
    __syncthreads();

    int n = blockIdx.x * 4 + warp;
    int nc = (n < n_nodes) ? n : (n_nodes - 1);
    int node = nodes[nc];
    int idx  = neigh_idx[nc * K + lane];
    float b3f = b3[0];

    // ---- layer 1 (exact fp32): h1 = relu(P[idx] + Q[node]); stage bf16 in A tile ----
    {
        const float4* Pr = (const float4*)(g_P + (size_t)idx * D);
        const float4* Qr = (const float4*)(g_Q + (size_t)node * D);
        unsigned char* dst = sA[warp] + lane * ASTRIDE_B;
#pragma unroll
        for (int i = 0; i < 8; i++) {
            float4 p0 = Pr[2 * i], q0 = Qr[2 * i];
            float4 p1 = Pr[2 * i + 1], q1 = Qr[2 * i + 1];
            uint4 w;
            CVT_BF16X2_F32(w.x, fmaxf(p0.x + q0.x, 0.f), fmaxf(p0.y + q0.y, 0.f));
            CVT_BF16X2_F32(w.y, fmaxf(p0.z + q0.z, 0.f), fmaxf(p0.w + q0.w, 0.f));
            CVT_BF16X2_F32(w.z, fmaxf(p1.x + q1.x, 0.f), fmaxf(p1.y + q1.y, 0.f));
            CVT_BF16X2_F32(w.w, fmaxf(p1.z + q1.z, 0.f), fmaxf(p1.w + q1.w, 0.f));
            *(uint4*)(dst + i * 16) = w;
        }
    }
    __syncwarp();

    // ---- A fragments (2 m-tiles x 4 k-steps) ----
    uint32_t af[2][4][4];
    uint32_t a_base = smem_to_u32(sA[warp]);
#pragma unroll
    for (int mt = 0; mt < 2; mt++)
#pragma unroll
        for (int ks = 0; ks < 4; ks++) {
            uint32_t addr = a_base + (mt * 16 + (lane & 15)) * ASTRIDE_B + ks * 32 + (lane >> 4) * 16;
            LDMATRIX_X4(af[mt][ks][0], af[mt][ks][1], af[mt][ks][2], af[mt][ks][3], addr);
        }

    // ---- layer 2 (HMMA) + layer 3 folded per n-tile ----
    uint32_t w_base = smem_to_u32(sW2);
    int j0l = 2 * (lane & 3);
    float sp0 = 0.f, sp1 = 0.f, sp2 = 0.f, sp3 = 0.f;   // rows l/4, 8+l/4, 16+l/4, 24+l/4
#pragma unroll
    for (int nt = 0; nt < 8; nt++) {
        uint32_t b[4][2];
        {
            uint32_t r0b, r1b, r2b, r3b;
            uint32_t addr = w_base + lane * ASTRIDE_B + nt * 16;
            LDMATRIX_X4_TRANS(r0b, r1b, r2b, r3b, addr);
            b[0][0] = r0b; b[0][1] = r1b; b[1][0] = r2b; b[1][1] = r3b;
            addr = w_base + (32 + lane) * ASTRIDE_B + nt * 16;
            LDMATRIX_X4_TRANS(r0b, r1b, r2b, r3b, addr);
            b[2][0] = r0b; b[2][1] = r1b; b[3][0] = r2b; b[3][1] = r3b;
        }
        int j = nt * 8 + j0l;
        float bb0 = sb2[j], bb1 = sb2[j + 1];
        float w30 = sW3[j], w31 = sW3[j + 1];
#pragma unroll
        for (int mt = 0; mt < 2; mt++) {
            float d0 = bb0, d1 = bb1, d2 = bb0, d3 = bb1;
#pragma unroll
            for (int ks = 0; ks < 4; ks++)
                MMA16816(d0, d1, d2, d3,
                         af[mt][ks][0], af[mt][ks][1], af[mt][ks][2], af[mt][ks][3],
                         b[ks][0], b[ks][1]);
            float lo = fmaf(fmaxf(d0, 0.f), w30, fmaf(fmaxf(d1, 0.f), w31, 0.f));
            float hi = fmaf(fmaxf(d2, 0.f), w30, fmaf(fmaxf(d3, 0.f), w31, 0.f));
            if (mt == 0) { sp0 += lo; sp1 += hi; } else { sp2 += lo; sp3 += hi; }
        }
    }
    // reduce over the 4 lanes sharing each row (lane bits 0-1)
    sp0 += __shfl_xor_sync(0xffffffffu, sp0, 1); sp0 += __shfl_xor_sync(0xffffffffu, sp0, 2);
    sp1 += __shfl_xor_sync(0xffffffffu, sp1, 1); sp1 += __shfl_xor_sync(0xffffffffu, sp1, 2);
    sp2 += __shfl_xor_sync(0xffffffffu, sp2, 1); sp2 += __shfl_xor_sync(0xffffffffu, sp2, 2);
    sp3 += __shfl_xor_sync(0xffffffffu, sp3, 1); sp3 += __shfl_xor_sync(0xffffffffu, sp3, 2);
    // redistribute: lane L wants score of row L
    int src = (lane & 7) * 4;
    float v0s = __shfl_sync(0xffffffffu, sp0, src);
    float v1s = __shfl_sync(0xffffffffu, sp1, src);
    float v2s = __shfl_sync(0xffffffffu, sp2, src);
    float v3s = __shfl_sync(0xffffffffu, sp3, src);
    float score = (lane < 8) ? v0s : (lane < 16) ? v1s : (lane < 24) ? v2s : v3s;
    score += b3f;

    // ---- masked softmax across warp ----
    unsigned int m = (g_mask[nc] >> lane) & 1u;
    float sc = m ? score : -1e30f;
    float mx = sc;
#pragma unroll
    for (int o = 16; o; o >>= 1) mx = fmaxf(mx, __shfl_xor_sync(0xffffffffu, mx, o));
    float e = __expf(sc - mx);
    float sum = e;
#pragma unroll
    for (int o = 16; o; o >>= 1) sum += __shfl_xor_sync(0xffffffffu, sum, o);
    float att = __fdividef(e, sum);

    // ---- out[n] = sum_k att_k * u2e[idx_k] (exact fp32) ----
    float part[D];
    {
        const float4* Er = (const float4*)(u2e + (size_t)idx * D);
#pragma unroll
        for (int i = 0; i < 16; i++) {
            float4 v = Er[i];
            part[4 * i + 0] = v.x * att;
            part[4 * i + 1] = v.y * att;
            part[4 * i + 2] = v.z * att;
            part[4 * i + 3] = v.w * att;
        }
    }
    rs_stage<16, 32>(part, lane);
    rs_stage<8, 16>(part, lane);
    rs_stage<4, 8>(part, lane);
    rs_stage<2, 4>(part, lane);
    rs_stage<1, 2>(part, lane);
    if (n < n_nodes)
        ((float2*)out)[n * 32 + lane] = make_float2(part[0], part[1]);
}

// ======================= launch =======================
// Input order (metadata): u2e, W1, b1, W2, b2, W3, b3, nodes, neigh_idx, neigh_mask
extern "C" void kernel_launch(void* const* d_in, const int* in_sizes, int n_in,
                              void* d_out, int out_size) {
    const float* u2e = (const float*)d_in[0];
    const float* W1  = (const float*)d_in[1];
    const float* b1  = (const float*)d_in[2];
    const float* W2  = (const float*)d_in[3];
    const float* b2  = (const float*)d_in[4];
    const float* W3  = (const float*)d_in[5];
    const float* b3  = (const float*)d_in[6];
    const int*   nodes     = (const int*)d_in[7];
    const int*   neigh_idx = (const int*)d_in[8];
    const void*  neigh_mask = d_in[9];
    float* out = (float*)d_out;

    int V = in_sizes[0] / D;
    if (V > VOCAB_MAX) V = VOCAB_MAX;
    int n_nodes = in_sizes[7];
    int n_words = in_sizes[9] / 4;

    mask_init_kernel<<<1, 1>>>();
    mask_detect_kernel<<<256, 256>>>((const unsigned int*)neigh_mask, n_words);
    mask_convert_kernel<<<(n_nodes + 255) / 256, 256>>>(neigh_mask, n_nodes);
    prep_mma_kernel<<<(V + 127) / 128, 128>>>(u2e, W1, b1, V);
    agg_mma_kernel<<<(n_nodes + 3) / 4, 128>>>(u2e, W2, b2, W3, b3,
                                               nodes, neigh_idx, out, n_nodes);
}

// round 7
// speedup vs baseline: 3.4188x; 1.4732x over previous
#include <cuda_runtime.h>
#include <cuda_bf16.h>
#include <cstdint>

#define D 64
#define K 32
#define VOCAB_MAX 100000

// Scratch (alloc-free rule): bf16 P/Q
__device__ unsigned short g_Pb[(size_t)VOCAB_MAX * D];   // bf16(u2e @ W1a)
__device__ unsigned short g_Qb[(size_t)VOCAB_MAX * D];   // bf16(u2e @ W1b + b1)
__device__ int g_flags[1];   // [0] != 0 -> mask buffer is bytes (else 32-bit words)

// ======================= helpers =======================
__device__ __forceinline__ uint32_t smem_to_u32(const void* p) {
    uint32_t a;
    asm("{ .reg .u64 t; cvta.to.shared.u64 t, %1; cvt.u32.u64 %0, t; }" : "=r"(a) : "l"(p));
    return a;
}
#define CVT_BF16X2_F32(result, a, b) \
    asm("cvt.rn.satfinite.bf16x2.f32 %0, %1, %2;" : "=r"(result) : "f"(b), "f"(a))
#define ADD_BF16X2(r, a, b) \
    asm("add.bf16x2 %0, %1, %2;" : "=r"(r) : "r"(a), "r"(b))
#define MAX_BF16X2(r, a, b) \
    asm("max.bf16x2 %0, %1, %2;" : "=r"(r) : "r"(a), "r"(b))

#define LDMATRIX_X4(r0, r1, r2, r3, addr) \
    asm volatile("ldmatrix.sync.aligned.m8n8.x4.shared.b16 {%0,%1,%2,%3}, [%4];" \
        : "=r"(r0), "=r"(r1), "=r"(r2), "=r"(r3) : "r"(addr))
#define LDMATRIX_X4_TRANS(r0, r1, r2, r3, addr) \
    asm volatile("ldmatrix.sync.aligned.m8n8.x4.trans.shared.b16 {%0,%1,%2,%3}, [%4];" \
        : "=r"(r0), "=r"(r1), "=r"(r2), "=r"(r3) : "r"(addr))

// D (f32) += A (bf16) x B (bf16); C==D accumulate in place
#define MMA16816(d0, d1, d2, d3, a0, a1, a2, a3, b0, b1) \
    asm volatile("mma.sync.aligned.m16n8k16.row.col.f32.bf16.bf16.f32 " \
        "{%0,%1,%2,%3}, {%4,%5,%6,%7}, {%8,%9}, {%0,%1,%2,%3};" \
        : "+f"(d0), "+f"(d1), "+f"(d2), "+f"(d3) \
        : "r"(a0), "r"(a1), "r"(a2), "r"(a3), "r"(b0), "r"(b1))

// A-tile SMEM: row stride 72 bf16 (144B) -> conflict-free ldmatrix
#define ASTRIDE_B 144

// ======================= prep: P/Q (bf16 out) + mask dtype scan =======================
// CTA = 4 warps; each warp computes 32 vocab rows. K=64, N=64, bf16 in/out, fp32 accum.
__global__ __launch_bounds__(128) void prep_mma_kernel(const float* __restrict__ u2e,
                                                       const float* __restrict__ W1,
                                                       const float* __restrict__ b1,
                                                       int V,
                                                       const unsigned int* __restrict__ mbuf,
                                                       int n_words) {
    __shared__ __align__(16) unsigned char sA[4][32 * ASTRIDE_B];
    __shared__ __align__(16) unsigned char sW[128 * ASTRIDE_B];  // W1 [128 k][64 n] bf16
    __shared__ float sb1[64];
    int tid = threadIdx.x, warp = tid >> 5, lane = tid & 31;

    // ---- mask dtype scan (byte vs word); flags are 0->1 idempotent across replays ----
    {
        int byte_mode = 0;
        for (int i = blockIdx.x * blockDim.x + tid; i < n_words; i += gridDim.x * blockDim.x) {
            unsigned int w = mbuf[i];
            if (w != 0u && w != 1u && w != 0x3f800000u) { byte_mode = 1; break; }
        }
        if (byte_mode) atomicOr(&g_flags[0], 1);
    }

    // ---- stage W1 (bf16, padded rows) ----
    for (int p = tid; p < 128 * 32; p += 128) {
        int r = p >> 5, cp = p & 31;
        uint32_t v;
        CVT_BF16X2_F32(v, W1[(size_t)r * 64 + 2 * cp], W1[(size_t)r * 64 + 2 * cp + 1]);
        *(uint32_t*)(sW + r * ASTRIDE_B + cp * 4) = v;
    }
    if (tid < 64) sb1[tid] = b1[tid];
    __syncthreads();

    int v0 = (blockIdx.x * 4 + warp) * 32;
    int vr = v0 + lane;
    int vc = (vr < V) ? vr : (V - 1);

    // Stage this lane's u2e row as bf16 into the warp's A tile
    {
        const float4* row = (const float4*)(u2e + (size_t)vc * D);
        unsigned char* dst = sA[warp] + lane * ASTRIDE_B;
#pragma unroll
        for (int i = 0; i < 8; i++) {
            float4 f0 = row[2 * i], f1 = row[2 * i + 1];
            uint4 w;
            CVT_BF16X2_F32(w.x, f0.x, f0.y);
            CVT_BF16X2_F32(w.y, f0.z, f0.w);
            CVT_BF16X2_F32(w.z, f1.x, f1.y);
            CVT_BF16X2_F32(w.w, f1.z, f1.w);
            *(uint4*)(dst + i * 16) = w;
        }
    }
    __syncwarp();

    // A fragments: 2 m-tiles x 4 k-steps
    uint32_t af[2][4][4];
    uint32_t a_base = smem_to_u32(sA[warp]);
#pragma unroll
    for (int mt = 0; mt < 2; mt++)
#pragma unroll
        for (int ks = 0; ks < 4; ks++) {
            uint32_t addr = a_base + (mt * 16 + (lane & 15)) * ASTRIDE_B + ks * 32 + (lane >> 4) * 16;
            LDMATRIX_X4(af[mt][ks][0], af[mt][ks][1], af[mt][ks][2], af[mt][ks][3], addr);
        }

    uint32_t w_base = smem_to_u32(sW);
    int j0 = 2 * (lane & 3);
    int r0 = lane >> 2;

#pragma unroll
    for (int half = 0; half < 2; half++) {
        unsigned short* gOut = half ? g_Qb : g_Pb;
#pragma unroll
        for (int nt = 0; nt < 8; nt++) {
            uint32_t b[4][2];
            {
                uint32_t r0b, r1b, r2b, r3b;
                uint32_t addr = w_base + (half * 64 + lane) * ASTRIDE_B + nt * 16;
                LDMATRIX_X4_TRANS(r0b, r1b, r2b, r3b, addr);
                b[0][0] = r0b; b[0][1] = r1b; b[1][0] = r2b; b[1][1] = r3b;
                addr = w_base + (half * 64 + 32 + lane) * ASTRIDE_B + nt * 16;
                LDMATRIX_X4_TRANS(r0b, r1b, r2b, r3b, addr);
                b[2][0] = r0b; b[2][1] = r1b; b[3][0] = r2b; b[3][1] = r3b;
            }
            int j = nt * 8 + j0;
            float init0 = half ? sb1[j] : 0.f;
            float init1 = half ? sb1[j + 1] : 0.f;
#pragma unroll
            for (int mt = 0; mt < 2; mt++) {
                float d0 = init0, d1 = init1, d2 = init0, d3 = init1;
#pragma unroll
                for (int ks = 0; ks < 4; ks++)
                    MMA16816(d0, d1, d2, d3,
                             af[mt][ks][0], af[mt][ks][1], af[mt][ks][2], af[mt][ks][3],
                             b[ks][0], b[ks][1]);
                int ra = v0 + mt * 16 + r0;
                int rb = ra + 8;
                uint32_t wlo, whi;
                CVT_BF16X2_F32(wlo, d0, d1);
                CVT_BF16X2_F32(whi, d2, d3);
                if (ra < V) *(uint32_t*)(gOut + (size_t)ra * D + j) = wlo;
                if (rb < V) *(uint32_t*)(gOut + (size_t)rb * D + j) = whi;
            }
        }
    }
}

// ---------------- reduce-scatter stage (array len = 2*HALF) ----------------
template <int OFF, int HALF>
__device__ __forceinline__ void rs_stage(float* part, int lane) {
    bool up = (lane & OFF) != 0;
#pragma unroll
    for (int j = 0; j < HALF; j++) {
        float send  = up ? part[j] : part[j + HALF];
        float other = __shfl_xor_sync(0xffffffffu, send, OFF);
        float keep  = up ? part[j + HALF] : part[j];
        part[j] = keep + other;
    }
}

// ======================= agg: persistent, one warp per node per iteration ==============
__global__ __launch_bounds__(256, 3) void agg_mma_kernel(
    const float* __restrict__ u2e,
    const float* __restrict__ W2, const float* __restrict__ b2,
    const float* __restrict__ W3, const float* __restrict__ b3,
    const int* __restrict__ nodes, const int* __restrict__ neigh_idx,
    const void* __restrict__ maskbuf,
    float* __restrict__ out, int n_nodes) {
    __shared__ __align__(16) unsigned char sA[8][32 * ASTRIDE_B];  // per-warp h1 tiles
    __shared__ __align__(16) unsigned char sW2[64 * ASTRIDE_B];    // W2 [64 k][64 n] bf16
    __shared__ float sb2[64];
    __shared__ float sW3[64];
    int tid = threadIdx.x, warp = tid >> 5, lane = tid & 31;

    for (int p = tid; p < 64 * 32; p += 256) {
        int r = p >> 5, cp = p & 31;
        uint32_t v;
        CVT_BF16X2_F32(v, W2[(size_t)r * 64 + 2 * cp], W2[(size_t)r * 64 + 2 * cp + 1]);
        *(uint32_t*)(sW2 + r * ASTRIDE_B + cp * 4) = v;
    }
    if (tid < 64) { sb2[tid] = b2[tid]; sW3[tid] = W3[tid]; }
    __syncthreads();

    const float b3f = b3[0];
    const int byte_mode = g_flags[0];
    uint32_t a_base = smem_to_u32(sA[warp]);
    uint32_t w_base = smem_to_u32(sW2);
    int j0l = 2 * (lane & 3);
    int wg = blockIdx.x * 8 + warp;
    int stride = gridDim.x * 8;

    for (int n = wg; n < n_nodes; n += stride) {
        int node = nodes[n];
        int idx  = neigh_idx[n * K + lane];

        // ---- layer 1 in bf16: A row = relu(P[idx] + Q[node]) -> SMEM tile ----
        {
            const uint4* Pr = (const uint4*)(g_Pb + (size_t)idx * D);
            const uint4* Qr = (const uint4*)(g_Qb + (size_t)node * D);
            unsigned char* dst = sA[warp] + lane * ASTRIDE_B;
#pragma unroll 2
            for (int i = 0; i < 8; i++) {
                uint4 p = Pr[i], q = Qr[i];
                uint4 w;
                ADD_BF16X2(w.x, p.x, q.x); MAX_BF16X2(w.x, w.x, 0u);
                ADD_BF16X2(w.y, p.y, q.y); MAX_BF16X2(w.y, w.y, 0u);
                ADD_BF16X2(w.z, p.z, q.z); MAX_BF16X2(w.z, w.z, 0u);
                ADD_BF16X2(w.w, p.w, q.w); MAX_BF16X2(w.w, w.w, 0u);
                *(uint4*)(dst + i * 16) = w;
            }
        }
        __syncwarp();

        // ---- A fragments (2 m-tiles x 4 k-steps) ----
        uint32_t af[2][4][4];
#pragma unroll
        for (int mt = 0; mt < 2; mt++)
#pragma unroll
            for (int ks = 0; ks < 4; ks++) {
                uint32_t addr = a_base + (mt * 16 + (lane & 15)) * ASTRIDE_B + ks * 32 + (lane >> 4) * 16;
                LDMATRIX_X4(af[mt][ks][0], af[mt][ks][1], af[mt][ks][2], af[mt][ks][3], addr);
            }

        // ---- layer 2 (HMMA) + layer 3 folded per n-tile ----
        float sp0 = 0.f, sp1 = 0.f, sp2 = 0.f, sp3 = 0.f;
#pragma unroll
        for (int nt = 0; nt < 8; nt++) {
            uint32_t b[4][2];
            {
                uint32_t r0b, r1b, r2b, r3b;
                uint32_t addr = w_base + lane * ASTRIDE_B + nt * 16;
                LDMATRIX_X4_TRANS(r0b, r1b, r2b, r3b, addr);
                b[0][0] = r0b; b[0][1] = r1b; b[1][0] = r2b; b[1][1] = r3b;
                addr = w_base + (32 + lane) * ASTRIDE_B + nt * 16;
                LDMATRIX_X4_TRANS(r0b, r1b, r2b, r3b, addr);
                b[2][0] = r0b; b[2][1] = r1b; b[3][0] = r2b; b[3][1] = r3b;
            }
            int j = nt * 8 + j0l;
            float bb0 = sb2[j], bb1 = sb2[j + 1];
            float w30 = sW3[j], w31 = sW3[j + 1];
#pragma unroll
            for (int mt = 0; mt < 2; mt++) {
                float d0 = bb0, d1 = bb1, d2 = bb0, d3 = bb1;
#pragma unroll
                for (int ks = 0; ks < 4; ks++)
                    MMA16816(d0, d1, d2, d3,
                             af[mt][ks][0], af[mt][ks][1], af[mt][ks][2], af[mt][ks][3],
                             b[ks][0], b[ks][1]);
                float lo = fmaf(fmaxf(d0, 0.f), w30, fmaf(fmaxf(d1, 0.f), w31, 0.f));
                float hi = fmaf(fmaxf(d2, 0.f), w30, fmaf(fmaxf(d3, 0.f), w31, 0.f));
                if (mt == 0) { sp0 += lo; sp1 += hi; } else { sp2 += lo; sp3 += hi; }
            }
        }
        sp0 += __shfl_xor_sync(0xffffffffu, sp0, 1); sp0 += __shfl_xor_sync(0xffffffffu, sp0, 2);
        sp1 += __shfl_xor_sync(0xffffffffu, sp1, 1); sp1 += __shfl_xor_sync(0xffffffffu, sp1, 2);
        sp2 += __shfl_xor_sync(0xffffffffu, sp2, 1); sp2 += __shfl_xor_sync(0xffffffffu, sp2, 2);
        sp3 += __shfl_xor_sync(0xffffffffu, sp3, 1); sp3 += __shfl_xor_sync(0xffffffffu, sp3, 2);
        int src = (lane & 7) * 4;
        float v0s = __shfl_sync(0xffffffffu, sp0, src);
        float v1s = __shfl_sync(0xffffffffu, sp1, src);
        float v2s = __shfl_sync(0xffffffffu, sp2, src);
        float v3s = __shfl_sync(0xffffffffu, sp3, src);
        float score = ((lane < 8) ? v0s : (lane < 16) ? v1s : (lane < 24) ? v2s : v3s) + b3f;

        // ---- mask bit straight from input buffer ----
        unsigned int m;
        if (byte_mode)
            m = ((const unsigned char*)maskbuf)[(size_t)n * K + lane] != 0;
        else
            m = ((const unsigned int*)maskbuf)[(size_t)n * K + lane] != 0u;

        // ---- masked softmax across warp ----
        float sc = m ? score : -1e30f;
        float mx = sc;
#pragma unroll
        for (int o = 16; o; o >>= 1) mx = fmaxf(mx, __shfl_xor_sync(0xffffffffu, mx, o));
        float e = __expf(sc - mx);
        float sum = e;
#pragma unroll
        for (int o = 16; o; o >>= 1) sum += __shfl_xor_sync(0xffffffffu, sum, o);
        float att = __fdividef(e, sum);

        // ---- out[n] = sum_k att_k * u2e[idx_k] (fp32), two 32-col chunks ----
#pragma unroll
        for (int c = 0; c < 2; c++) {
            const float4* Er = (const float4*)(u2e + (size_t)idx * D + c * 32);
            float part[32];
#pragma unroll
            for (int i = 0; i < 8; i++) {
                float4 v = Er[i];
                part[4 * i + 0] = v.x * att;
                part[4 * i + 1] = v.y * att;
                part[4 * i + 2] = v.z * att;
                part[4 * i + 3] = v.w * att;
            }
            rs_stage<16, 16>(part, lane);
            rs_stage<8, 8>(part, lane);
            rs_stage<4, 4>(part, lane);
            rs_stage<2, 2>(part, lane);
            rs_stage<1, 1>(part, lane);
            out[(size_t)n * D + c * 32 + lane] = part[0];   // lane L owns column L
        }
    }
}

// ======================= launch =======================
// Input order (metadata): u2e, W1, b1, W2, b2, W3, b3, nodes, neigh_idx, neigh_mask
extern "C" void kernel_launch(void* const* d_in, const int* in_sizes, int n_in,
                              void* d_out, int out_size) {
    const float* u2e = (const float*)d_in[0];
    const float* W1  = (const float*)d_in[1];
    const float* b1  = (const float*)d_in[2];
    const float* W2  = (const float*)d_in[3];
    const float* b2  = (const float*)d_in[4];
    const float* W3  = (const float*)d_in[5];
    const float* b3  = (const float*)d_in[6];
    const int*   nodes     = (const int*)d_in[7];
    const int*   neigh_idx = (const int*)d_in[8];
    const void*  neigh_mask = d_in[9];
    float* out = (float*)d_out;

    int V = in_sizes[0] / D;
    if (V > VOCAB_MAX) V = VOCAB_MAX;
    int n_nodes = in_sizes[7];
    int n_words = in_sizes[9] / 4;   // safe lower bound under both dtypes

    prep_mma_kernel<<<(V + 127) / 128, 128>>>(u2e, W1, b1, V,
                                              (const unsigned int*)neigh_mask, n_words);
    int grid = 888;
    agg_mma_kernel<<<grid, 256>>>(u2e, W2, b2, W3, b3,
                                  nodes, neigh_idx, neigh_mask, out, n_nodes);
}

// round 8
// speedup vs baseline: 5.8503x; 1.7112x over previous
#include <cuda_runtime.h>
#include <cuda_bf16.h>
#include <cstdint>

#define D 64
#define K 32
#define VOCAB_MAX 100000

// Scratch (alloc-free rule): bf16 P/Q
__device__ unsigned short g_Pb[(size_t)VOCAB_MAX * D];   // bf16(u2e @ W1a)
__device__ unsigned short g_Qb[(size_t)VOCAB_MAX * D];   // bf16(u2e @ W1b + b1)
__device__ int g_flags[1];   // [0] != 0 -> mask buffer is bytes (else 32-bit words)

// ======================= helpers =======================
__device__ __forceinline__ uint32_t smem_to_u32(const void* p) {
    uint32_t a;
    asm("{ .reg .u64 t; cvta.to.shared.u64 t, %1; cvt.u32.u64 %0, t; }" : "=r"(a) : "l"(p));
    return a;
}
#define CVT_BF16X2_F32(result, a, b) \
    asm("cvt.rn.satfinite.bf16x2.f32 %0, %1, %2;" : "=r"(result) : "f"(b), "f"(a))
#define ADD_BF16X2(r, a, b) \
    asm("add.bf16x2 %0, %1, %2;" : "=r"(r) : "r"(a), "r"(b))
#define MAX_BF16X2(r, a, b) \
    asm("max.bf16x2 %0, %1, %2;" : "=r"(r) : "r"(a), "r"(b))

#define LDMATRIX_X4(r0, r1, r2, r3, addr) \
    asm volatile("ldmatrix.sync.aligned.m8n8.x4.shared.b16 {%0,%1,%2,%3}, [%4];" \
        : "=r"(r0), "=r"(r1), "=r"(r2), "=r"(r3) : "r"(addr))
#define LDMATRIX_X4_TRANS(r0, r1, r2, r3, addr) \
    asm volatile("ldmatrix.sync.aligned.m8n8.x4.trans.shared.b16 {%0,%1,%2,%3}, [%4];" \
        : "=r"(r0), "=r"(r1), "=r"(r2), "=r"(r3) : "r"(addr))

// D (f32) += A (bf16) x B (bf16); C==D accumulate in place
#define MMA16816(d0, d1, d2, d3, a0, a1, a2, a3, b0, b1) \
    asm volatile("mma.sync.aligned.m16n8k16.row.col.f32.bf16.bf16.f32 " \
        "{%0,%1,%2,%3}, {%4,%5,%6,%7}, {%8,%9}, {%0,%1,%2,%3};" \
        : "+f"(d0), "+f"(d1), "+f"(d2), "+f"(d3) \
        : "r"(a0), "r"(a1), "r"(a2), "r"(a3), "r"(b0), "r"(b1))

// A-tile SMEM: row stride 72 bf16 (144B) -> conflict-free ldmatrix
#define ASTRIDE_B 144

// ======================= prep: P/Q (bf16 out) + mask dtype scan =======================
__global__ __launch_bounds__(128) void prep_mma_kernel(const float* __restrict__ u2e,
                                                       const float* __restrict__ W1,
                                                       const float* __restrict__ b1,
                                                       int V,
                                                       const unsigned int* __restrict__ mbuf,
                                                       int n_words) {
    __shared__ __align__(16) unsigned char sA[4][32 * ASTRIDE_B];
    __shared__ __align__(16) unsigned char sW[128 * ASTRIDE_B];  // W1 [128 k][64 n] bf16
    __shared__ float sb1[64];
    int tid = threadIdx.x, warp = tid >> 5, lane = tid & 31;

    // ---- mask dtype scan (byte vs word); 0->1 idempotent across graph replays ----
    {
        int byte_mode = 0;
        for (int i = blockIdx.x * blockDim.x + tid; i < n_words; i += gridDim.x * blockDim.x) {
            unsigned int w = mbuf[i];
            if (w != 0u && w != 1u && w != 0x3f800000u) { byte_mode = 1; break; }
        }
        if (byte_mode) atomicOr(&g_flags[0], 1);
    }

    // ---- stage W1 (bf16, padded rows) ----
    for (int p = tid; p < 128 * 32; p += 128) {
        int r = p >> 5, cp = p & 31;
        uint32_t v;
        CVT_BF16X2_F32(v, W1[(size_t)r * 64 + 2 * cp], W1[(size_t)r * 64 + 2 * cp + 1]);
        *(uint32_t*)(sW + r * ASTRIDE_B + cp * 4) = v;
    }
    if (tid < 64) sb1[tid] = b1[tid];
    __syncthreads();

    int v0 = (blockIdx.x * 4 + warp) * 32;
    int vr = v0 + lane;
    int vc = (vr < V) ? vr : (V - 1);

    // Stage this lane's u2e row as bf16 into the warp's A tile
    {
        const float4* row = (const float4*)(u2e + (size_t)vc * D);
        unsigned char* dst = sA[warp] + lane * ASTRIDE_B;
#pragma unroll
        for (int i = 0; i < 8; i++) {
            float4 f0 = row[2 * i], f1 = row[2 * i + 1];
            uint4 w;
            CVT_BF16X2_F32(w.x, f0.x, f0.y);
            CVT_BF16X2_F32(w.y, f0.z, f0.w);
            CVT_BF16X2_F32(w.z, f1.x, f1.y);
            CVT_BF16X2_F32(w.w, f1.z, f1.w);
            *(uint4*)(dst + i * 16) = w;
        }
    }
    __syncwarp();

    uint32_t af[2][4][4];
    uint32_t a_base = smem_to_u32(sA[warp]);
#pragma unroll
    for (int mt = 0; mt < 2; mt++)
#pragma unroll
        for (int ks = 0; ks < 4; ks++) {
            uint32_t addr = a_base + (mt * 16 + (lane & 15)) * ASTRIDE_B + ks * 32 + (lane >> 4) * 16;
            LDMATRIX_X4(af[mt][ks][0], af[mt][ks][1], af[mt][ks][2], af[mt][ks][3], addr);
        }

    uint32_t w_base = smem_to_u32(sW);
    int j0 = 2 * (lane & 3);
    int r0 = lane >> 2;

#pragma unroll
    for (int half = 0; half < 2; half++) {
        unsigned short* gOut = half ? g_Qb : g_Pb;
#pragma unroll
        for (int nt = 0; nt < 8; nt++) {
            uint32_t b[4][2];
            {
                uint32_t r0b, r1b, r2b, r3b;
                uint32_t addr = w_base + (half * 64 + lane) * ASTRIDE_B + nt * 16;
                LDMATRIX_X4_TRANS(r0b, r1b, r2b, r3b, addr);
                b[0][0] = r0b; b[0][1] = r1b; b[1][0] = r2b; b[1][1] = r3b;
                addr = w_base + (half * 64 + 32 + lane) * ASTRIDE_B + nt * 16;
                LDMATRIX_X4_TRANS(r0b, r1b, r2b, r3b, addr);
                b[2][0] = r0b; b[2][1] = r1b; b[3][0] = r2b; b[3][1] = r3b;
            }
            int j = nt * 8 + j0;
            float init0 = half ? sb1[j] : 0.f;
            float init1 = half ? sb1[j + 1] : 0.f;
#pragma unroll
            for (int mt = 0; mt < 2; mt++) {
                float d0 = init0, d1 = init1, d2 = init0, d3 = init1;
#pragma unroll
                for (int ks = 0; ks < 4; ks++)
                    MMA16816(d0, d1, d2, d3,
                             af[mt][ks][0], af[mt][ks][1], af[mt][ks][2], af[mt][ks][3],
                             b[ks][0], b[ks][1]);
                int ra = v0 + mt * 16 + r0;
                int rb = ra + 8;
                uint32_t wlo, whi;
                CVT_BF16X2_F32(wlo, d0, d1);
                CVT_BF16X2_F32(whi, d2, d3);
                if (ra < V) *(uint32_t*)(gOut + (size_t)ra * D + j) = wlo;
                if (rb < V) *(uint32_t*)(gOut + (size_t)rb * D + j) = whi;
            }
        }
    }
}

// ======================= agg: persistent, one warp per node per iteration ==============
// All gathers are warp-cooperative (each LDG touches <=4 cache lines).
__global__ __launch_bounds__(256, 3) void agg_mma_kernel(
    const float* __restrict__ u2e,
    const float* __restrict__ W2, const float* __restrict__ b2,
    const float* __restrict__ W3, const float* __restrict__ b3,
    const int* __restrict__ nodes, const int* __restrict__ neigh_idx,
    const void* __restrict__ maskbuf,
    float* __restrict__ out, int n_nodes) {
    __shared__ __align__(16) unsigned char sA[8][32 * ASTRIDE_B];  // per-warp h1 tiles
    __shared__ __align__(16) unsigned char sW2[64 * ASTRIDE_B];    // W2 [64 k][64 n] bf16
    __shared__ float sb2[64];
    __shared__ float sW3[64];
    int tid = threadIdx.x, warp = tid >> 5, lane = tid & 31;

    for (int p = tid; p < 64 * 32; p += 256) {
        int r = p >> 5, cp = p & 31;
        uint32_t v;
        CVT_BF16X2_F32(v, W2[(size_t)r * 64 + 2 * cp], W2[(size_t)r * 64 + 2 * cp + 1]);
        *(uint32_t*)(sW2 + r * ASTRIDE_B + cp * 4) = v;
    }
    if (tid < 64) { sb2[tid] = b2[tid]; sW3[tid] = W3[tid]; }
    __syncthreads();

    const float b3f = b3[0];
    const int byte_mode = g_flags[0];
    uint32_t a_base = smem_to_u32(sA[warp]);
    uint32_t w_base = smem_to_u32(sW2);
    const int j0l = 2 * (lane & 3);
    const int seg = lane & 7;        // 16B segment within a 128B bf16 row
    const int rsub = lane >> 3;      // 0..3 (row within a 4-row load group)
    const int erow_sub = lane >> 4;  // 0..1 (row parity for epilogue)
    const int ecol = (lane & 15) * 4;
    int wg = blockIdx.x * 8 + warp;
    int stride = gridDim.x * 8;

    for (int n = wg; n < n_nodes; n += stride) {
        int node = nodes[n];
        int idx  = neigh_idx[n * K + lane];

        // ---- layer 1 bf16, cooperative: A[row] = relu(P[idx_row] + Q[node]) ----
        {
            uint4 q4 = *(const uint4*)(g_Qb + (size_t)node * D + seg * 8);
            unsigned char* aw = sA[warp];
#pragma unroll
            for (int it = 0; it < 8; it++) {
                int row = it * 4 + rsub;
                int ridx = __shfl_sync(0xffffffffu, idx, row);
                uint4 p4 = *(const uint4*)(g_Pb + (size_t)ridx * D + seg * 8);
                uint4 w;
                ADD_BF16X2(w.x, p4.x, q4.x); MAX_BF16X2(w.x, w.x, 0u);
                ADD_BF16X2(w.y, p4.y, q4.y); MAX_BF16X2(w.y, w.y, 0u);
                ADD_BF16X2(w.z, p4.z, q4.z); MAX_BF16X2(w.z, w.z, 0u);
                ADD_BF16X2(w.w, p4.w, q4.w); MAX_BF16X2(w.w, w.w, 0u);
                *(uint4*)(aw + row * ASTRIDE_B + seg * 16) = w;
            }
        }
        __syncwarp();

        // ---- A fragments (2 m-tiles x 4 k-steps) ----
        uint32_t af[2][4][4];
#pragma unroll
        for (int mt = 0; mt < 2; mt++)
#pragma unroll
            for (int ks = 0; ks < 4; ks++) {
                uint32_t addr = a_base + (mt * 16 + (lane & 15)) * ASTRIDE_B + ks * 32 + (lane >> 4) * 16;
                LDMATRIX_X4(af[mt][ks][0], af[mt][ks][1], af[mt][ks][2], af[mt][ks][3], addr);
            }

        // ---- layer 2 (HMMA) + layer 3 folded per n-tile ----
        float sp0 = 0.f, sp1 = 0.f, sp2 = 0.f, sp3 = 0.f;
#pragma unroll
        for (int nt = 0; nt < 8; nt++) {
            uint32_t b[4][2];
            {
                uint32_t r0b, r1b, r2b, r3b;
                uint32_t addr = w_base + lane * ASTRIDE_B + nt * 16;
                LDMATRIX_X4_TRANS(r0b, r1b, r2b, r3b, addr);
                b[0][0] = r0b; b[0][1] = r1b; b[1][0] = r2b; b[1][1] = r3b;
                addr = w_base + (32 + lane) * ASTRIDE_B + nt * 16;
                LDMATRIX_X4_TRANS(r0b, r1b, r2b, r3b, addr);
                b[2][0] = r0b; b[2][1] = r1b; b[3][0] = r2b; b[3][1] = r3b;
            }
            int j = nt * 8 + j0l;
            float bb0 = sb2[j], bb1 = sb2[j + 1];
            float w30 = sW3[j], w31 = sW3[j + 1];
#pragma unroll
            for (int mt = 0; mt < 2; mt++) {
                float d0 = bb0, d1 = bb1, d2 = bb0, d3 = bb1;
#pragma unroll
                for (int ks = 0; ks < 4; ks++)
                    MMA16816(d0, d1, d2, d3,
                             af[mt][ks][0], af[mt][ks][1], af[mt][ks][2], af[mt][ks][3],
                             b[ks][0], b[ks][1]);
                float lo = fmaf(fmaxf(d0, 0.f), w30, fmaf(fmaxf(d1, 0.f), w31, 0.f));
                float hi = fmaf(fmaxf(d2, 0.f), w30, fmaf(fmaxf(d3, 0.f), w31, 0.f));
                if (mt == 0) { sp0 += lo; sp1 += hi; } else { sp2 += lo; sp3 += hi; }
            }
        }
        sp0 += __shfl_xor_sync(0xffffffffu, sp0, 1); sp0 += __shfl_xor_sync(0xffffffffu, sp0, 2);
        sp1 += __shfl_xor_sync(0xffffffffu, sp1, 1); sp1 += __shfl_xor_sync(0xffffffffu, sp1, 2);
        sp2 += __shfl_xor_sync(0xffffffffu, sp2, 1); sp2 += __shfl_xor_sync(0xffffffffu, sp2, 2);
        sp3 += __shfl_xor_sync(0xffffffffu, sp3, 1); sp3 += __shfl_xor_sync(0xffffffffu, sp3, 2);
        int src = (lane & 7) * 4;
        float v0s = __shfl_sync(0xffffffffu, sp0, src);
        float v1s = __shfl_sync(0xffffffffu, sp1, src);
        float v2s = __shfl_sync(0xffffffffu, sp2, src);
        float v3s = __shfl_sync(0xffffffffu, sp3, src);
        float score = ((lane < 8) ? v0s : (lane < 16) ? v1s : (lane < 24) ? v2s : v3s) + b3f;

        // ---- mask bit straight from input buffer ----
        unsigned int m;
        if (byte_mode)
            m = ((const unsigned char*)maskbuf)[(size_t)n * K + lane] != 0;
        else
            m = ((const unsigned int*)maskbuf)[(size_t)n * K + lane] != 0u;

        // ---- masked softmax across warp (masked lanes -> att exactly 0) ----
        float sc = m ? score : -1e30f;
        float mx = sc;
#pragma unroll
        for (int o = 16; o; o >>= 1) mx = fmaxf(mx, __shfl_xor_sync(0xffffffffu, mx, o));
        float e = __expf(sc - mx);
        float sum = e;
#pragma unroll
        for (int o = 16; o; o >>= 1) sum += __shfl_xor_sync(0xffffffffu, sum, o);
        float att = __fdividef(e, sum);

        // ---- epilogue, cooperative: out[cols] = sum_r att_r * u2e[idx_r][cols] ----
        float a0 = 0.f, a1 = 0.f, a2 = 0.f, a3 = 0.f;
#pragma unroll
        for (int it = 0; it < 16; it++) {
            int row = it * 2 + erow_sub;
            float attr = __shfl_sync(0xffffffffu, att, row);
            int ridx = __shfl_sync(0xffffffffu, idx, row);
            float4 v = *(const float4*)(u2e + (size_t)ridx * D + ecol);
            a0 = fmaf(attr, v.x, a0);
            a1 = fmaf(attr, v.y, a1);
            a2 = fmaf(attr, v.z, a2);
            a3 = fmaf(attr, v.w, a3);
        }
        a0 += __shfl_xor_sync(0xffffffffu, a0, 16);
        a1 += __shfl_xor_sync(0xffffffffu, a1, 16);
        a2 += __shfl_xor_sync(0xffffffffu, a2, 16);
        a3 += __shfl_xor_sync(0xffffffffu, a3, 16);
        if (lane < 16)
            *(float4*)(out + (size_t)n * D + ecol) = make_float4(a0, a1, a2, a3);
    }
}

// ======================= launch =======================
// Input order (metadata): u2e, W1, b1, W2, b2, W3, b3, nodes, neigh_idx, neigh_mask
extern "C" void kernel_launch(void* const* d_in, const int* in_sizes, int n_in,
                              void* d_out, int out_size) {
    const float* u2e = (const float*)d_in[0];
    const float* W1  = (const float*)d_in[1];
    const float* b1  = (const float*)d_in[2];
    const float* W2  = (const float*)d_in[3];
    const float* b2  = (const float*)d_in[4];
    const float* W3  = (const float*)d_in[5];
    const float* b3  = (const float*)d_in[6];
    const int*   nodes     = (const int*)d_in[7];
    const int*   neigh_idx = (const int*)d_in[8];
    const void*  neigh_mask = d_in[9];
    float* out = (float*)d_out;

    int V = in_sizes[0] / D;
    if (V > VOCAB_MAX) V = VOCAB_MAX;
    int n_nodes = in_sizes[7];
    int n_words = in_sizes[9] / 4;   // safe lower bound under both dtypes

    prep_mma_kernel<<<(V + 127) / 128, 128>>>(u2e, W1, b1, V,
                                              (const unsigned int*)neigh_mask, n_words);
    agg_mma_kernel<<<888, 256>>>(u2e, W2, b2, W3, b3,
                                 nodes, neigh_idx, neigh_mask, out, n_nodes);
}

// round 9
// speedup vs baseline: 6.7107x; 1.1471x over previous
#include <cuda_runtime.h>
#include <cuda_bf16.h>
#include <cstdint>

#define D 64
#define K 32
#define VOCAB_MAX 100000

// Scratch (alloc-free rule): bf16 P/Q
__device__ unsigned short g_Pb[(size_t)VOCAB_MAX * D];   // bf16(u2e @ W1a)
__device__ unsigned short g_Qb[(size_t)VOCAB_MAX * D];   // bf16(u2e @ W1b + b1)
__device__ int g_flags[1];   // [0] != 0 -> mask buffer is bytes (else 32-bit words)

// ======================= helpers =======================
__device__ __forceinline__ uint32_t smem_to_u32(const void* p) {
    uint32_t a;
    asm("{ .reg .u64 t; cvta.to.shared.u64 t, %1; cvt.u32.u64 %0, t; }" : "=r"(a) : "l"(p));
    return a;
}
#define CVT_BF16X2_F32(result, a, b) \
    asm("cvt.rn.satfinite.bf16x2.f32 %0, %1, %2;" : "=r"(result) : "f"(b), "f"(a))
#define ADD_BF16X2(r, a, b) \
    asm("add.bf16x2 %0, %1, %2;" : "=r"(r) : "r"(a), "r"(b))
#define MAX_BF16X2(r, a, b) \
    asm("max.bf16x2 %0, %1, %2;" : "=r"(r) : "r"(a), "r"(b))

#define LDMATRIX_X4(r0, r1, r2, r3, addr) \
    asm volatile("ldmatrix.sync.aligned.m8n8.x4.shared.b16 {%0,%1,%2,%3}, [%4];" \
        : "=r"(r0), "=r"(r1), "=r"(r2), "=r"(r3) : "r"(addr))
#define LDMATRIX_X4_TRANS(r0, r1, r2, r3, addr) \
    asm volatile("ldmatrix.sync.aligned.m8n8.x4.trans.shared.b16 {%0,%1,%2,%3}, [%4];" \
        : "=r"(r0), "=r"(r1), "=r"(r2), "=r"(r3) : "r"(addr))

// D (f32) += A (bf16) x B (bf16); C==D accumulate in place
#define MMA16816(d0, d1, d2, d3, a0, a1, a2, a3, b0, b1) \
    asm volatile("mma.sync.aligned.m16n8k16.row.col.f32.bf16.bf16.f32 " \
        "{%0,%1,%2,%3}, {%4,%5,%6,%7}, {%8,%9}, {%0,%1,%2,%3};" \
        : "+f"(d0), "+f"(d1), "+f"(d2), "+f"(d3) \
        : "r"(a0), "r"(a1), "r"(a2), "r"(a3), "r"(b0), "r"(b1))

// A-tile SMEM: row stride 72 bf16 (144B) -> conflict-free ldmatrix
#define ASTRIDE_B 144

// ======================= prep: P/Q (bf16 out) + mask dtype scan =======================
__global__ __launch_bounds__(128) void prep_mma_kernel(const float* __restrict__ u2e,
                                                       const float* __restrict__ W1,
                                                       const float* __restrict__ b1,
                                                       int V,
                                                       const unsigned int* __restrict__ mbuf,
                                                       int n_words) {
    __shared__ __align__(16) unsigned char sA[4][32 * ASTRIDE_B];
    __shared__ __align__(16) unsigned char sW[128 * ASTRIDE_B];  // W1 [128 k][64 n] bf16
    __shared__ float sb1[64];
    int tid = threadIdx.x, warp = tid >> 5, lane = tid & 31;

    // ---- mask dtype scan (byte vs word); 0->1 idempotent across graph replays ----
    {
        int byte_mode = 0;
        for (int i = blockIdx.x * blockDim.x + tid; i < n_words; i += gridDim.x * blockDim.x) {
            unsigned int w = mbuf[i];
            if (w != 0u && w != 1u && w != 0x3f800000u) { byte_mode = 1; break; }
        }
        if (byte_mode) atomicOr(&g_flags[0], 1);
    }

    // ---- stage W1 (bf16, padded rows) ----
    for (int p = tid; p < 128 * 32; p += 128) {
        int r = p >> 5, cp = p & 31;
        uint32_t v;
        CVT_BF16X2_F32(v, W1[(size_t)r * 64 + 2 * cp], W1[(size_t)r * 64 + 2 * cp + 1]);
        *(uint32_t*)(sW + r * ASTRIDE_B + cp * 4) = v;
    }
    if (tid < 64) sb1[tid] = b1[tid];
    __syncthreads();

    int v0 = (blockIdx.x * 4 + warp) * 32;
    int vr = v0 + lane;
    int vc = (vr < V) ? vr : (V - 1);

    // Stage this lane's u2e row as bf16 into the warp's A tile
    {
        const float4* row = (const float4*)(u2e + (size_t)vc * D);
        unsigned char* dst = sA[warp] + lane * ASTRIDE_B;
#pragma unroll
        for (int i = 0; i < 8; i++) {
            float4 f0 = row[2 * i], f1 = row[2 * i + 1];
            uint4 w;
            CVT_BF16X2_F32(w.x, f0.x, f0.y);
            CVT_BF16X2_F32(w.y, f0.z, f0.w);
            CVT_BF16X2_F32(w.z, f1.x, f1.y);
            CVT_BF16X2_F32(w.w, f1.z, f1.w);
            *(uint4*)(dst + i * 16) = w;
        }
    }
    __syncwarp();

    uint32_t af[2][4][4];
    uint32_t a_base = smem_to_u32(sA[warp]);
#pragma unroll
    for (int mt = 0; mt < 2; mt++)
#pragma unroll
        for (int ks = 0; ks < 4; ks++) {
            uint32_t addr = a_base + (mt * 16 + (lane & 15)) * ASTRIDE_B + ks * 32 + (lane >> 4) * 16;
            LDMATRIX_X4(af[mt][ks][0], af[mt][ks][1], af[mt][ks][2], af[mt][ks][3], addr);
        }

    uint32_t w_base = smem_to_u32(sW);
    int j0 = 2 * (lane & 3);
    int r0 = lane >> 2;

#pragma unroll
    for (int half = 0; half < 2; half++) {
        unsigned short* gOut = half ? g_Qb : g_Pb;
#pragma unroll
        for (int nt = 0; nt < 8; nt++) {
            uint32_t b[4][2];
            {
                uint32_t r0b, r1b, r2b, r3b;
                uint32_t addr = w_base + (half * 64 + lane) * ASTRIDE_B + nt * 16;
                LDMATRIX_X4_TRANS(r0b, r1b, r2b, r3b, addr);
                b[0][0] = r0b; b[0][1] = r1b; b[1][0] = r2b; b[1][1] = r3b;
                addr = w_base + (half * 64 + 32 + lane) * ASTRIDE_B + nt * 16;
                LDMATRIX_X4_TRANS(r0b, r1b, r2b, r3b, addr);
                b[2][0] = r0b; b[2][1] = r1b; b[3][0] = r2b; b[3][1] = r3b;
            }
            int j = nt * 8 + j0;
            float init0 = half ? sb1[j] : 0.f;
            float init1 = half ? sb1[j + 1] : 0.f;
#pragma unroll
            for (int mt = 0; mt < 2; mt++) {
                float d0 = init0, d1 = init1, d2 = init0, d3 = init1;
#pragma unroll
                for (int ks = 0; ks < 4; ks++)
                    MMA16816(d0, d1, d2, d3,
                             af[mt][ks][0], af[mt][ks][1], af[mt][ks][2], af[mt][ks][3],
                             b[ks][0], b[ks][1]);
                int ra = v0 + mt * 16 + r0;
                int rb = ra + 8;
                uint32_t wlo, whi;
                CVT_BF16X2_F32(wlo, d0, d1);
                CVT_BF16X2_F32(whi, d2, d3);
                if (ra < V) *(uint32_t*)(gOut + (size_t)ra * D + j) = wlo;
                if (rb < V) *(uint32_t*)(gOut + (size_t)rb * D + j) = whi;
            }
        }
    }
}

// ======================= agg: persistent; B (W2) fragments hoisted to registers =========
__global__ __launch_bounds__(256, 2) void agg_mma_kernel(
    const float* __restrict__ u2e,
    const float* __restrict__ W2, const float* __restrict__ b2,
    const float* __restrict__ W3, const float* __restrict__ b3,
    const int* __restrict__ nodes, const int* __restrict__ neigh_idx,
    const void* __restrict__ maskbuf,
    float* __restrict__ out, int n_nodes) {
    __shared__ __align__(16) unsigned char sA[8][32 * ASTRIDE_B];  // per-warp h1 tiles
    __shared__ __align__(16) unsigned char sW2[64 * ASTRIDE_B];    // W2 staging (bf16)
    __shared__ float sb2[64];
    __shared__ float sW3[64];
    int tid = threadIdx.x, warp = tid >> 5, lane = tid & 31;

    for (int p = tid; p < 64 * 32; p += 256) {
        int r = p >> 5, cp = p & 31;
        uint32_t v;
        CVT_BF16X2_F32(v, W2[(size_t)r * 64 + 2 * cp], W2[(size_t)r * 64 + 2 * cp + 1]);
        *(uint32_t*)(sW2 + r * ASTRIDE_B + cp * 4) = v;
    }
    if (tid < 64) { sb2[tid] = b2[tid]; sW3[tid] = W3[tid]; }
    __syncthreads();

    // ---- hoist ALL B fragments into registers (loop-invariant W2) ----
    uint32_t bf[8][4][2];
    {
        uint32_t w_base = smem_to_u32(sW2);
#pragma unroll
        for (int nt = 0; nt < 8; nt++) {
            uint32_t r0b, r1b, r2b, r3b;
            uint32_t addr = w_base + lane * ASTRIDE_B + nt * 16;
            LDMATRIX_X4_TRANS(r0b, r1b, r2b, r3b, addr);
            bf[nt][0][0] = r0b; bf[nt][0][1] = r1b; bf[nt][1][0] = r2b; bf[nt][1][1] = r3b;
            addr = w_base + (32 + lane) * ASTRIDE_B + nt * 16;
            LDMATRIX_X4_TRANS(r0b, r1b, r2b, r3b, addr);
            bf[nt][2][0] = r0b; bf[nt][2][1] = r1b; bf[nt][3][0] = r2b; bf[nt][3][1] = r3b;
        }
    }

    const float b3f = b3[0];
    const int byte_mode = g_flags[0];
    uint32_t a_base = smem_to_u32(sA[warp]);
    const int j0l = 2 * (lane & 3);
    const int seg = lane & 7;        // 16B segment within a 128B bf16 row
    const int rsub = lane >> 3;      // 0..3 (row within a 4-row load group)
    const int erow_sub = lane >> 4;  // 0..1 (row parity for epilogue)
    const int ecol = (lane & 15) * 4;
    int wg = blockIdx.x * 8 + warp;
    int stride = gridDim.x * 8;

    for (int n = wg; n < n_nodes; n += stride) {
        int node = nodes[n];
        int idx  = neigh_idx[n * K + lane];

        // ---- mask bit (issued early, consumed at softmax) ----
        unsigned int m;
        if (byte_mode)
            m = ((const unsigned char*)maskbuf)[(size_t)n * K + lane] != 0;
        else
            m = ((const unsigned int*)maskbuf)[(size_t)n * K + lane] != 0u;

        // ---- layer 1 bf16, cooperative: A[row] = relu(P[idx_row] + Q[node]) ----
        {
            uint4 q4 = *(const uint4*)(g_Qb + (size_t)node * D + seg * 8);
            unsigned char* aw = sA[warp];
#pragma unroll
            for (int it = 0; it < 8; it++) {
                int row = it * 4 + rsub;
                int ridx = __shfl_sync(0xffffffffu, idx, row);
                uint4 p4 = *(const uint4*)(g_Pb + (size_t)ridx * D + seg * 8);
                uint4 w;
                ADD_BF16X2(w.x, p4.x, q4.x); MAX_BF16X2(w.x, w.x, 0u);
                ADD_BF16X2(w.y, p4.y, q4.y); MAX_BF16X2(w.y, w.y, 0u);
                ADD_BF16X2(w.z, p4.z, q4.z); MAX_BF16X2(w.z, w.z, 0u);
                ADD_BF16X2(w.w, p4.w, q4.w); MAX_BF16X2(w.w, w.w, 0u);
                *(uint4*)(aw + row * ASTRIDE_B + seg * 16) = w;
            }
        }
        __syncwarp();

        // ---- A fragments (2 m-tiles x 4 k-steps) ----
        uint32_t af[2][4][4];
#pragma unroll
        for (int mt = 0; mt < 2; mt++)
#pragma unroll
            for (int ks = 0; ks < 4; ks++) {
                uint32_t addr = a_base + (mt * 16 + (lane & 15)) * ASTRIDE_B + ks * 32 + (lane >> 4) * 16;
                LDMATRIX_X4(af[mt][ks][0], af[mt][ks][1], af[mt][ks][2], af[mt][ks][3], addr);
            }

        // ---- layer 2 (HMMA, B from registers) + layer 3 folded per n-tile ----
        float sp0 = 0.f, sp1 = 0.f, sp2 = 0.f, sp3 = 0.f;
#pragma unroll
        for (int nt = 0; nt < 8; nt++) {
            int j = nt * 8 + j0l;
            float bb0 = sb2[j], bb1 = sb2[j + 1];
            float w30 = sW3[j], w31 = sW3[j + 1];
#pragma unroll
            for (int mt = 0; mt < 2; mt++) {
                float d0 = bb0, d1 = bb1, d2 = bb0, d3 = bb1;
#pragma unroll
                for (int ks = 0; ks < 4; ks++)
                    MMA16816(d0, d1, d2, d3,
                             af[mt][ks][0], af[mt][ks][1], af[mt][ks][2], af[mt][ks][3],
                             bf[nt][ks][0], bf[nt][ks][1]);
                float lo = fmaf(fmaxf(d0, 0.f), w30, fmaf(fmaxf(d1, 0.f), w31, 0.f));
                float hi = fmaf(fmaxf(d2, 0.f), w30, fmaf(fmaxf(d3, 0.f), w31, 0.f));
                if (mt == 0) { sp0 += lo; sp1 += hi; } else { sp2 += lo; sp3 += hi; }
            }
        }
        sp0 += __shfl_xor_sync(0xffffffffu, sp0, 1); sp0 += __shfl_xor_sync(0xffffffffu, sp0, 2);
        sp1 += __shfl_xor_sync(0xffffffffu, sp1, 1); sp1 += __shfl_xor_sync(0xffffffffu, sp1, 2);
        sp2 += __shfl_xor_sync(0xffffffffu, sp2, 1); sp2 += __shfl_xor_sync(0xffffffffu, sp2, 2);
        sp3 += __shfl_xor_sync(0xffffffffu, sp3, 1); sp3 += __shfl_xor_sync(0xffffffffu, sp3, 2);
        int src = (lane & 7) * 4;
        float v0s = __shfl_sync(0xffffffffu, sp0, src);
        float v1s = __shfl_sync(0xffffffffu, sp1, src);
        float v2s = __shfl_sync(0xffffffffu, sp2, src);
        float v3s = __shfl_sync(0xffffffffu, sp3, src);
        float score = ((lane < 8) ? v0s : (lane < 16) ? v1s : (lane < 24) ? v2s : v3s) + b3f;

        // ---- masked softmax across warp (masked lanes -> att exactly 0) ----
        float sc = m ? score : -1e30f;
        float mx = sc;
#pragma unroll
        for (int o = 16; o; o >>= 1) mx = fmaxf(mx, __shfl_xor_sync(0xffffffffu, mx, o));
        float e = __expf(sc - mx);
        float sum = e;
#pragma unroll
        for (int o = 16; o; o >>= 1) sum += __shfl_xor_sync(0xffffffffu, sum, o);
        float att = __fdividef(e, sum);

        // ---- epilogue, cooperative: out[cols] = sum_r att_r * u2e[idx_r][cols] ----
        float a0 = 0.f, a1 = 0.f, a2 = 0.f, a3 = 0.f;
#pragma unroll
        for (int it = 0; it < 16; it++) {
            int row = it * 2 + erow_sub;
            float attr = __shfl_sync(0xffffffffu, att, row);
            int ridx = __shfl_sync(0xffffffffu, idx, row);
            float4 v = *(const float4*)(u2e + (size_t)ridx * D + ecol);
            a0 = fmaf(attr, v.x, a0);
            a1 = fmaf(attr, v.y, a1);
            a2 = fmaf(attr, v.z, a2);
            a3 = fmaf(attr, v.w, a3);
        }
        a0 += __shfl_xor_sync(0xffffffffu, a0, 16);
        a1 += __shfl_xor_sync(0xffffffffu, a1, 16);
        a2 += __shfl_xor_sync(0xffffffffu, a2, 16);
        a3 += __shfl_xor_sync(0xffffffffu, a3, 16);
        if (lane < 16)
            *(float4*)(out + (size_t)n * D + ecol) = make_float4(a0, a1, a2, a3);
    }
}

// ======================= launch =======================
// Input order (metadata): u2e, W1, b1, W2, b2, W3, b3, nodes, neigh_idx, neigh_mask
extern "C" void kernel_launch(void* const* d_in, const int* in_sizes, int n_in,
                              void* d_out, int out_size) {
    const float* u2e = (const float*)d_in[0];
    const float* W1  = (const float*)d_in[1];
    const float* b1  = (const float*)d_in[2];
    const float* W2  = (const float*)d_in[3];
    const float* b2  = (const float*)d_in[4];
    const float* W3  = (const float*)d_in[5];
    const float* b3  = (const float*)d_in[6];
    const int*   nodes     = (const int*)d_in[7];
    const int*   neigh_idx = (const int*)d_in[8];
    const void*  neigh_mask = d_in[9];
    float* out = (float*)d_out;

    int V = in_sizes[0] / D;
    if (V > VOCAB_MAX) V = VOCAB_MAX;
    int n_nodes = in_sizes[7];
    int n_words = in_sizes[9] / 4;   // safe lower bound under both dtypes

    prep_mma_kernel<<<(V + 127) / 128, 128>>>(u2e, W1, b1, V,
                                              (const unsigned int*)neigh_mask, n_words);
    agg_mma_kernel<<<888, 256>>>(u2e, W2, b2, W3, b3,
                                 nodes, neigh_idx, neigh_mask, out, n_nodes);
}

// round 10
// speedup vs baseline: 7.6915x; 1.1462x over previous
#include <cuda_runtime.h>
#include <cuda_bf16.h>
#include <cstdint>

#define D 64
#define K 32
#define VOCAB_MAX 100000

// Scratch (alloc-free rule): bf16 P/Q
__device__ unsigned short g_Pb[(size_t)VOCAB_MAX * D];   // bf16(u2e @ W1a)
__device__ unsigned short g_Qb[(size_t)VOCAB_MAX * D];   // bf16(u2e @ W1b + b1)
__device__ int g_flags[1];   // [0] != 0 -> mask buffer is bytes (else 32-bit words)

// ======================= helpers =======================
__device__ __forceinline__ uint32_t smem_to_u32(const void* p) {
    uint32_t a;
    asm("{ .reg .u64 t; cvta.to.shared.u64 t, %1; cvt.u32.u64 %0, t; }" : "=r"(a) : "l"(p));
    return a;
}
#define CVT_BF16X2_F32(result, a, b) \
    asm("cvt.rn.satfinite.bf16x2.f32 %0, %1, %2;" : "=r"(result) : "f"(b), "f"(a))
#define ADD_BF16X2(r, a, b) \
    asm("add.bf16x2 %0, %1, %2;" : "=r"(r) : "r"(a), "r"(b))
#define MAX_BF16X2(r, a, b) \
    asm("max.bf16x2 %0, %1, %2;" : "=r"(r) : "r"(a), "r"(b))

#define LDMATRIX_X4(r0, r1, r2, r3, addr) \
    asm volatile("ldmatrix.sync.aligned.m8n8.x4.shared.b16 {%0,%1,%2,%3}, [%4];" \
        : "=r"(r0), "=r"(r1), "=r"(r2), "=r"(r3) : "r"(addr))
#define LDMATRIX_X4_TRANS(r0, r1, r2, r3, addr) \
    asm volatile("ldmatrix.sync.aligned.m8n8.x4.trans.shared.b16 {%0,%1,%2,%3}, [%4];" \
        : "=r"(r0), "=r"(r1), "=r"(r2), "=r"(r3) : "r"(addr))

// D (f32) += A (bf16) x B (bf16); C==D accumulate in place
#define MMA16816(d0, d1, d2, d3, a0, a1, a2, a3, b0, b1) \
    asm volatile("mma.sync.aligned.m16n8k16.row.col.f32.bf16.bf16.f32 " \
        "{%0,%1,%2,%3}, {%4,%5,%6,%7}, {%8,%9}, {%0,%1,%2,%3};" \
        : "+f"(d0), "+f"(d1), "+f"(d2), "+f"(d3) \
        : "r"(a0), "r"(a1), "r"(a2), "r"(a3), "r"(b0), "r"(b1))

// A-tile SMEM: row stride 72 bf16 (144B) -> conflict-free ldmatrix
#define ASTRIDE_B 144

// ======================= prep: P/Q (bf16 out) + mask dtype scan =======================
__global__ __launch_bounds__(128) void prep_mma_kernel(const float* __restrict__ u2e,
                                                       const float* __restrict__ W1,
                                                       const float* __restrict__ b1,
                                                       int V,
                                                       const unsigned int* __restrict__ mbuf,
                                                       int n_words) {
    __shared__ __align__(16) unsigned char sA[4][32 * ASTRIDE_B];
    __shared__ __align__(16) unsigned char sW[128 * ASTRIDE_B];  // W1 [128 k][64 n] bf16
    __shared__ float sb1[64];
    int tid = threadIdx.x, warp = tid >> 5, lane = tid & 31;

    // ---- mask dtype scan (byte vs word); 0->1 idempotent across graph replays ----
    {
        int byte_mode = 0;
        for (int i = blockIdx.x * blockDim.x + tid; i < n_words; i += gridDim.x * blockDim.x) {
            unsigned int w = mbuf[i];
            if (w != 0u && w != 1u && w != 0x3f800000u) { byte_mode = 1; break; }
        }
        if (byte_mode) atomicOr(&g_flags[0], 1);
    }

    // ---- stage W1 (bf16, padded rows) ----
    for (int p = tid; p < 128 * 32; p += 128) {
        int r = p >> 5, cp = p & 31;
        uint32_t v;
        CVT_BF16X2_F32(v, W1[(size_t)r * 64 + 2 * cp], W1[(size_t)r * 64 + 2 * cp + 1]);
        *(uint32_t*)(sW + r * ASTRIDE_B + cp * 4) = v;
    }
    if (tid < 64) sb1[tid] = b1[tid];
    __syncthreads();

    int v0 = (blockIdx.x * 4 + warp) * 32;
    int vr = v0 + lane;
    int vc = (vr < V) ? vr : (V - 1);

    // Stage this lane's u2e row as bf16 into the warp's A tile
    {
        const float4* row = (const float4*)(u2e + (size_t)vc * D);
        unsigned char* dst = sA[warp] + lane * ASTRIDE_B;
#pragma unroll
        for (int i = 0; i < 8; i++) {
            float4 f0 = row[2 * i], f1 = row[2 * i + 1];
            uint4 w;
            CVT_BF16X2_F32(w.x, f0.x, f0.y);
            CVT_BF16X2_F32(w.y, f0.z, f0.w);
            CVT_BF16X2_F32(w.z, f1.x, f1.y);
            CVT_BF16X2_F32(w.w, f1.z, f1.w);
            *(uint4*)(dst + i * 16) = w;
        }
    }
    __syncwarp();

    uint32_t af[2][4][4];
    uint32_t a_base = smem_to_u32(sA[warp]);
#pragma unroll
    for (int mt = 0; mt < 2; mt++)
#pragma unroll
        for (int ks = 0; ks < 4; ks++) {
            uint32_t addr = a_base + (mt * 16 + (lane & 15)) * ASTRIDE_B + ks * 32 + (lane >> 4) * 16;
            LDMATRIX_X4(af[mt][ks][0], af[mt][ks][1], af[mt][ks][2], af[mt][ks][3], addr);
        }

    uint32_t w_base = smem_to_u32(sW);
    int j0 = 2 * (lane & 3);
    int r0 = lane >> 2;

#pragma unroll
    for (int half = 0; half < 2; half++) {
        unsigned short* gOut = half ? g_Qb : g_Pb;
#pragma unroll
        for (int nt = 0; nt < 8; nt++) {
            uint32_t b[4][2];
            {
                uint32_t r0b, r1b, r2b, r3b;
                uint32_t addr = w_base + (half * 64 + lane) * ASTRIDE_B + nt * 16;
                LDMATRIX_X4_TRANS(r0b, r1b, r2b, r3b, addr);
                b[0][0] = r0b; b[0][1] = r1b; b[1][0] = r2b; b[1][1] = r3b;
                addr = w_base + (half * 64 + 32 + lane) * ASTRIDE_B + nt * 16;
                LDMATRIX_X4_TRANS(r0b, r1b, r2b, r3b, addr);
                b[2][0] = r0b; b[2][1] = r1b; b[3][0] = r2b; b[3][1] = r3b;
            }
            int j = nt * 8 + j0;
            float init0 = half ? sb1[j] : 0.f;
            float init1 = half ? sb1[j + 1] : 0.f;
#pragma unroll
            for (int mt = 0; mt < 2; mt++) {
                float d0 = init0, d1 = init1, d2 = init0, d3 = init1;
#pragma unroll
                for (int ks = 0; ks < 4; ks++)
                    MMA16816(d0, d1, d2, d3,
                             af[mt][ks][0], af[mt][ks][1], af[mt][ks][2], af[mt][ks][3],
                             b[ks][0], b[ks][1]);
                int ra = v0 + mt * 16 + r0;
                int rb = ra + 8;
                uint32_t wlo, whi;
                CVT_BF16X2_F32(wlo, d0, d1);
                CVT_BF16X2_F32(whi, d2, d3);
                if (ra < V) *(uint32_t*)(gOut + (size_t)ra * D + j) = wlo;
                if (rb < V) *(uint32_t*)(gOut + (size_t)rb * D + j) = whi;
            }
        }
    }
}

// ======================= agg: persistent; software-pipelined gathers ====================
// B fragments half-hoisted (nt 0-3 in regs, 4-7 via ldmatrix); next node's P rows
// prefetched into registers during current node's MMA/softmax/epilogue.
__global__ __launch_bounds__(256, 2) void agg_mma_kernel(
    const float* __restrict__ u2e,
    const float* __restrict__ W2, const float* __restrict__ b2,
    const float* __restrict__ W3, const float* __restrict__ b3,
    const int* __restrict__ nodes, const int* __restrict__ neigh_idx,
    const void* __restrict__ maskbuf,
    float* __restrict__ out, int n_nodes) {
    __shared__ __align__(16) unsigned char sA[8][32 * ASTRIDE_B];  // per-warp h1 tiles
    __shared__ __align__(16) unsigned char sW2[64 * ASTRIDE_B];    // W2 staging (bf16)
    __shared__ float sb2[64];
    __shared__ float sW3[64];
    int tid = threadIdx.x, warp = tid >> 5, lane = tid & 31;

    for (int p = tid; p < 64 * 32; p += 256) {
        int r = p >> 5, cp = p & 31;
        uint32_t v;
        CVT_BF16X2_F32(v, W2[(size_t)r * 64 + 2 * cp], W2[(size_t)r * 64 + 2 * cp + 1]);
        *(uint32_t*)(sW2 + r * ASTRIDE_B + cp * 4) = v;
    }
    if (tid < 64) { sb2[tid] = b2[tid]; sW3[tid] = W3[tid]; }
    __syncthreads();

    uint32_t w_base = smem_to_u32(sW2);

    // ---- hoist B fragments for n-tiles 0..3 only (register budget) ----
    uint32_t bfh[4][4][2];
#pragma unroll
    for (int nt = 0; nt < 4; nt++) {
        uint32_t r0b, r1b, r2b, r3b;
        uint32_t addr = w_base + lane * ASTRIDE_B + nt * 16;
        LDMATRIX_X4_TRANS(r0b, r1b, r2b, r3b, addr);
        bfh[nt][0][0] = r0b; bfh[nt][0][1] = r1b; bfh[nt][1][0] = r2b; bfh[nt][1][1] = r3b;
        addr = w_base + (32 + lane) * ASTRIDE_B + nt * 16;
        LDMATRIX_X4_TRANS(r0b, r1b, r2b, r3b, addr);
        bfh[nt][2][0] = r0b; bfh[nt][2][1] = r1b; bfh[nt][3][0] = r2b; bfh[nt][3][1] = r3b;
    }

    const float b3f = b3[0];
    const int byte_mode = g_flags[0];
    uint32_t a_base = smem_to_u32(sA[warp]);
    const int j0l = 2 * (lane & 3);
    const int seg = lane & 7;        // 16B segment within a 128B bf16 row
    const int rsub = lane >> 3;      // 0..3 (row within a 4-row load group)
    const int erow_sub = lane >> 4;  // 0..1 (row parity for epilogue)
    const int ecol = (lane & 15) * 4;
    int wg = blockIdx.x * 8 + warp;
    int stride = gridDim.x * 8;

    if (wg >= n_nodes) return;

    // ---- pipeline prologue: front-end for the first node ----
    int idx, m;
    uint4 q4, p4[8];
    {
        int node = nodes[wg];
        idx = neigh_idx[wg * K + lane];
        if (byte_mode)
            m = ((const unsigned char*)maskbuf)[(size_t)wg * K + lane] != 0;
        else
            m = ((const unsigned int*)maskbuf)[(size_t)wg * K + lane] != 0u;
        q4 = *(const uint4*)(g_Qb + (size_t)node * D + seg * 8);
#pragma unroll
        for (int it = 0; it < 8; it++) {
            int ridx = __shfl_sync(0xffffffffu, idx, it * 4 + rsub);
            p4[it] = *(const uint4*)(g_Pb + (size_t)ridx * D + seg * 8);
        }
    }

    for (int n = wg; n < n_nodes; n += stride) {
        // ---- layer 1: consume prefetched P/Q -> relu -> A tile ----
        {
            unsigned char* aw = sA[warp];
#pragma unroll
            for (int it = 0; it < 8; it++) {
                uint4 w;
                ADD_BF16X2(w.x, p4[it].x, q4.x); MAX_BF16X2(w.x, w.x, 0u);
                ADD_BF16X2(w.y, p4[it].y, q4.y); MAX_BF16X2(w.y, w.y, 0u);
                ADD_BF16X2(w.z, p4[it].z, q4.z); MAX_BF16X2(w.z, w.z, 0u);
                ADD_BF16X2(w.w, p4[it].w, q4.w); MAX_BF16X2(w.w, w.w, 0u);
                *(uint4*)(aw + (it * 4 + rsub) * ASTRIDE_B + seg * 16) = w;
            }
        }
        __syncwarp();

        // ---- prefetch next node's front-end (overlaps MMA/softmax/epilogue) ----
        int n2 = n + stride;
        int nc2 = (n2 < n_nodes) ? n2 : n;
        int idx2 = neigh_idx[(size_t)nc2 * K + lane];
        int m2;
        if (byte_mode)
            m2 = ((const unsigned char*)maskbuf)[(size_t)nc2 * K + lane] != 0;
        else
            m2 = ((const unsigned int*)maskbuf)[(size_t)nc2 * K + lane] != 0u;
        int node2 = nodes[nc2];
        uint4 q42 = *(const uint4*)(g_Qb + (size_t)node2 * D + seg * 8);
        uint4 p42[8];
#pragma unroll
        for (int it = 0; it < 8; it++) {
            int ridx = __shfl_sync(0xffffffffu, idx2, it * 4 + rsub);
            p42[it] = *(const uint4*)(g_Pb + (size_t)ridx * D + seg * 8);
        }

        // ---- A fragments (2 m-tiles x 4 k-steps) ----
        uint32_t af[2][4][4];
#pragma unroll
        for (int mt = 0; mt < 2; mt++)
#pragma unroll
            for (int ks = 0; ks < 4; ks++) {
                uint32_t addr = a_base + (mt * 16 + (lane & 15)) * ASTRIDE_B + ks * 32 + (lane >> 4) * 16;
                LDMATRIX_X4(af[mt][ks][0], af[mt][ks][1], af[mt][ks][2], af[mt][ks][3], addr);
            }

        // ---- layer 2 (HMMA) + layer 3 folded per n-tile ----
        float sp0 = 0.f, sp1 = 0.f, sp2 = 0.f, sp3 = 0.f;
#pragma unroll
        for (int nt = 0; nt < 8; nt++) {
            uint32_t b[4][2];
            if (nt < 4) {
#pragma unroll
                for (int ks = 0; ks < 4; ks++) { b[ks][0] = bfh[nt][ks][0]; b[ks][1] = bfh[nt][ks][1]; }
            } else {
                uint32_t r0b, r1b, r2b, r3b;
                uint32_t addr = w_base + lane * ASTRIDE_B + nt * 16;
                LDMATRIX_X4_TRANS(r0b, r1b, r2b, r3b, addr);
                b[0][0] = r0b; b[0][1] = r1b; b[1][0] = r2b; b[1][1] = r3b;
                addr = w_base + (32 + lane) * ASTRIDE_B + nt * 16;
                LDMATRIX_X4_TRANS(r0b, r1b, r2b, r3b, addr);
                b[2][0] = r0b; b[2][1] = r1b; b[3][0] = r2b; b[3][1] = r3b;
            }
            int j = nt * 8 + j0l;
            float bb0 = sb2[j], bb1 = sb2[j + 1];
            float w30 = sW3[j], w31 = sW3[j + 1];
#pragma unroll
            for (int mt = 0; mt < 2; mt++) {
                float d0 = bb0, d1 = bb1, d2 = bb0, d3 = bb1;
#pragma unroll
                for (int ks = 0; ks < 4; ks++)
                    MMA16816(d0, d1, d2, d3,
                             af[mt][ks][0], af[mt][ks][1], af[mt][ks][2], af[mt][ks][3],
                             b[ks][0], b[ks][1]);
                float lo = fmaf(fmaxf(d0, 0.f), w30, fmaf(fmaxf(d1, 0.f), w31, 0.f));
                float hi = fmaf(fmaxf(d2, 0.f), w30, fmaf(fmaxf(d3, 0.f), w31, 0.f));
                if (mt == 0) { sp0 += lo; sp1 += hi; } else { sp2 += lo; sp3 += hi; }
            }
        }
        sp0 += __shfl_xor_sync(0xffffffffu, sp0, 1); sp0 += __shfl_xor_sync(0xffffffffu, sp0, 2);
        sp1 += __shfl_xor_sync(0xffffffffu, sp1, 1); sp1 += __shfl_xor_sync(0xffffffffu, sp1, 2);
        sp2 += __shfl_xor_sync(0xffffffffu, sp2, 1); sp2 += __shfl_xor_sync(0xffffffffu, sp2, 2);
        sp3 += __shfl_xor_sync(0xffffffffu, sp3, 1); sp3 += __shfl_xor_sync(0xffffffffu, sp3, 2);
        int src = (lane & 7) * 4;
        float v0s = __shfl_sync(0xffffffffu, sp0, src);
        float v1s = __shfl_sync(0xffffffffu, sp1, src);
        float v2s = __shfl_sync(0xffffffffu, sp2, src);
        float v3s = __shfl_sync(0xffffffffu, sp3, src);
        float score = ((lane < 8) ? v0s : (lane < 16) ? v1s : (lane < 24) ? v2s : v3s) + b3f;

        // ---- masked softmax across warp (masked lanes -> att exactly 0) ----
        float sc = m ? score : -1e30f;
        float mx = sc;
#pragma unroll
        for (int o = 16; o; o >>= 1) mx = fmaxf(mx, __shfl_xor_sync(0xffffffffu, mx, o));
        float e = __expf(sc - mx);
        float sum = e;
#pragma unroll
        for (int o = 16; o; o >>= 1) sum += __shfl_xor_sync(0xffffffffu, sum, o);
        float att = __fdividef(e, sum);

        // ---- epilogue, cooperative: out[cols] = sum_r att_r * u2e[idx_r][cols] ----
        float a0 = 0.f, a1 = 0.f, a2 = 0.f, a3 = 0.f;
#pragma unroll
        for (int it = 0; it < 16; it++) {
            int row = it * 2 + erow_sub;
            float attr = __shfl_sync(0xffffffffu, att, row);
            int ridx = __shfl_sync(0xffffffffu, idx, row);
            float4 v = *(const float4*)(u2e + (size_t)ridx * D + ecol);
            a0 = fmaf(attr, v.x, a0);
            a1 = fmaf(attr, v.y, a1);
            a2 = fmaf(attr, v.z, a2);
            a3 = fmaf(attr, v.w, a3);
        }
        a0 += __shfl_xor_sync(0xffffffffu, a0, 16);
        a1 += __shfl_xor_sync(0xffffffffu, a1, 16);
        a2 += __shfl_xor_sync(0xffffffffu, a2, 16);
        a3 += __shfl_xor_sync(0xffffffffu, a3, 16);
        if (lane < 16)
            *(float4*)(out + (size_t)n * D + ecol) = make_float4(a0, a1, a2, a3);

        // ---- rotate pipeline registers ----
        idx = idx2; m = m2; q4 = q42;
#pragma unroll
        for (int it = 0; it < 8; it++) p4[it] = p42[it];
    }
}

// ======================= launch =======================
// Input order (metadata): u2e, W1, b1, W2, b2, W3, b3, nodes, neigh_idx, neigh_mask
extern "C" void kernel_launch(void* const* d_in, const int* in_sizes, int n_in,
                              void* d_out, int out_size) {
    const float* u2e = (const float*)d_in[0];
    const float* W1  = (const float*)d_in[1];
    const float* b1  = (const float*)d_in[2];
    const float* W2  = (const float*)d_in[3];
    const float* b2  = (const float*)d_in[4];
    const float* W3  = (const float*)d_in[5];
    const float* b3  = (const float*)d_in[6];
    const int*   nodes     = (const int*)d_in[7];
    const int*   neigh_idx = (const int*)d_in[8];
    const void*  neigh_mask = d_in[9];
    float* out = (float*)d_out;

    int V = in_sizes[0] / D;
    if (V > VOCAB_MAX) V = VOCAB_MAX;
    int n_nodes = in_sizes[7];
    int n_words = in_sizes[9] / 4;   // safe lower bound under both dtypes

    prep_mma_kernel<<<(V + 127) / 128, 128>>>(u2e, W1, b1, V,
                                              (const unsigned int*)neigh_mask, n_words);
    agg_mma_kernel<<<296, 256>>>(u2e, W2, b2, W3, b3,
                                 nodes, neigh_idx, neigh_mask, out, n_nodes);
}